// round 2
// baseline (speedup 1.0000x reference)
#include <cuda_runtime.h>
#include <cstdint>
#include <cstdio>

// ---------------- problem constants ----------------
#define BB_ 2
#define TT_ 2048
#define CC_ 1024
#define HH_ 16
#define DD_ 64

// exp(s/8) = 2^(s * log2(e)/8)
#define SOFTMAX_SCL 0.18033688011112042f

// ---------------- scratch (tf32 bit patterns stored as unsigned) ----------------
__device__ unsigned g_Xt[BB_*TT_*CC_];        // X pre-converted
__device__ unsigned g_Wt[4*CC_*CC_];          // Wq|Wk|Wv|Wo pre-converted
__device__ unsigned g_Q [BB_*HH_*TT_*DD_];    // [b,h,t,d] tf32
__device__ unsigned g_K [BB_*HH_*TT_*DD_];
__device__ unsigned g_V [BB_*HH_*TT_*DD_];
__device__ unsigned g_Yc[BB_*TT_*CC_];        // merged heads [b,t,c] tf32

// ---------------- helpers ----------------
__device__ __forceinline__ unsigned f2tf(float x) {
    unsigned r;
    asm("cvt.rna.tf32.f32 %0, %1;" : "=r"(r) : "f"(x));
    return r;
}
__device__ __forceinline__ float ex2(float x) {
    float y;
    asm("ex2.approx.f32 %0, %1;" : "=f"(y) : "f"(x));
    return y;
}
__device__ __forceinline__ void mma8(float* d, const unsigned* a, const unsigned* b) {
    asm volatile(
        "mma.sync.aligned.m16n8k8.row.col.f32.tf32.tf32.f32 "
        "{%0,%1,%2,%3},{%4,%5,%6,%7},{%8,%9},{%0,%1,%2,%3};"
        : "+f"(d[0]), "+f"(d[1]), "+f"(d[2]), "+f"(d[3])
        : "r"(a[0]), "r"(a[1]), "r"(a[2]), "r"(a[3]),
          "r"(b[0]), "r"(b[1]));
}
__device__ __forceinline__ void cpa(unsigned dst, const void* src) {
    asm volatile("cp.async.cg.shared.global [%0], [%1], 16;" :: "r"(dst), "l"(src));
}
#define CP_COMMIT() asm volatile("cp.async.commit_group;")
#define CP_WAIT1()  asm volatile("cp.async.wait_group 1;")
#define CP_WAIT0()  asm volatile("cp.async.wait_group 0;")

// ============================================================================
// one-shot tf32 pre-conversion: X (1M float4) + 4 weights (256K float4 each)
// ============================================================================
__global__ void __launch_bounds__(256) conv_kernel(
    const float4* __restrict__ X,  const float4* __restrict__ Wq,
    const float4* __restrict__ Wk, const float4* __restrict__ Wv,
    const float4* __restrict__ Wo)
{
    int i = blockIdx.x * 256 + threadIdx.x;          // 0 .. 2M-1
    const float4* src;
    uint4* dst;
    if (i < (1 << 20)) {
        src = X + i;
        dst = (uint4*)g_Xt + i;
    } else {
        int j = i - (1 << 20);
        int w = j >> 18, r = j & 0x3FFFF;
        const float4* s4 = (w == 0) ? Wq : (w == 1) ? Wk : (w == 2) ? Wv : Wo;
        src = s4 + r;
        dst = (uint4*)g_Wt + (w << 18) + r;
    }
    float4 v = *src;
    *dst = make_uint4(f2tf(v.x), f2tf(v.y), f2tf(v.z), f2tf(v.w));
}

// ============================================================================
// GEMM: C[m,n] = sum_k A[m,k] * B[n,k]  — inputs already tf32 bits.
// 128x128x32 tiles, 256 thr (8 warps 2x4, warp tile 64x32),
// 2-stage cp.async double buffering.
// MODE 1: A=g_Xt, B=g_Wt(q|k|v); epilogue scatters tf32 to g_Q/g_K/g_V.
// MODE 0: A=g_Yc, B=Wo slice; epilogue writes fp32 Cout.
// ============================================================================
#define GSTG (128*36)
#define GEMM_SMEM_BYTES (4*GSTG*4)

template<int MODE>
__global__ void __launch_bounds__(256, 2) gemm_nt(
    const unsigned* __restrict__ A,
    const unsigned* __restrict__ B,
    float* __restrict__ Cout)
{
    extern __shared__ unsigned smem[];
    unsigned* sA = smem;            // [2][128*36]
    unsigned* sB = smem + 2*GSTG;   // [2][128*36]
    const unsigned sbase = (unsigned)__cvta_generic_to_shared(smem);

    const int tid  = threadIdx.x;
    const int bm   = blockIdx.y * 128;
    const int bn   = blockIdx.x * 128;
    const int warp = tid >> 5, lane = tid & 31;
    const int g = lane >> 2, t = lane & 3;
    const int wm = (warp & 1) * 64;
    const int wn = (warp >> 1) * 32;

    const unsigned* Ap = A + (size_t)bm * 1024;
    const unsigned* Bp = B + (size_t)bn * 1024;   // works for both modes

    // per-thread load coords: 4 rows-of-float4 for A, 4 for B
    const int lr = tid >> 3;             // 0..31 base row
    const int lc = (tid & 7) * 4;        // 0..28 col

    float acc[4][4][4];
    #pragma unroll
    for (int i = 0; i < 4; i++)
        #pragma unroll
        for (int j = 0; j < 4; j++)
            #pragma unroll
            for (int r = 0; r < 4; r++) acc[i][j][r] = 0.f;

    // ---- prologue: stage 0 ----
    #pragma unroll
    for (int i = 0; i < 4; i++) {
        int r = lr + i * 32;
        cpa(sbase + (r*36 + lc)*4,            Ap + (size_t)r*1024 + lc);
        cpa(sbase + (2*GSTG + r*36 + lc)*4,   Bp + (size_t)r*1024 + lc);
    }
    CP_COMMIT();

    int cur = 0;
    for (int k0 = 0; k0 < 1024; k0 += 32) {
        if (k0 + 32 < 1024) {
            int nxt = cur ^ 1;
            #pragma unroll
            for (int i = 0; i < 4; i++) {
                int r = lr + i * 32;
                cpa(sbase + (nxt*GSTG + r*36 + lc)*4,
                    Ap + (size_t)r*1024 + k0 + 32 + lc);
                cpa(sbase + ((2+nxt)*GSTG + r*36 + lc)*4,
                    Bp + (size_t)r*1024 + k0 + 32 + lc);
            }
            CP_COMMIT();
            CP_WAIT1();
        } else {
            CP_WAIT0();
        }
        __syncthreads();

        const unsigned* cA = sA + cur*GSTG;
        const unsigned* cB = sB + cur*GSTG;
        #pragma unroll
        for (int ks = 0; ks < 32; ks += 8) {
            unsigned afr[4][4], bfr[4][2];
            #pragma unroll
            for (int im = 0; im < 4; im++) {
                int base = wm + im * 16;
                afr[im][0] = cA[(base + g    ) * 36 + ks + t    ];
                afr[im][1] = cA[(base + g + 8) * 36 + ks + t    ];
                afr[im][2] = cA[(base + g    ) * 36 + ks + t + 4];
                afr[im][3] = cA[(base + g + 8) * 36 + ks + t + 4];
            }
            #pragma unroll
            for (int in = 0; in < 4; in++) {
                int nb = wn + in * 8 + g;
                bfr[in][0] = cB[nb * 36 + ks + t    ];
                bfr[in][1] = cB[nb * 36 + ks + t + 4];
            }
            #pragma unroll
            for (int im = 0; im < 4; im++)
                #pragma unroll
                for (int in = 0; in < 4; in++)
                    mma8(acc[im][in], afr[im], bfr[in]);
        }
        __syncthreads();
        cur ^= 1;
    }

    // ---------------- epilogue ----------------
    if (MODE == 0) {
        #pragma unroll
        for (int im = 0; im < 4; im++) {
            #pragma unroll
            for (int in = 0; in < 4; in++) {
                int r0 = bm + wm + im * 16 + g;
                int c0 = bn + wn + in * 8 + 2 * t;
                *(float2*)(Cout + (size_t)r0 * 1024 + c0) =
                    make_float2(acc[im][in][0], acc[im][in][1]);
                *(float2*)(Cout + (size_t)(r0 + 8) * 1024 + c0) =
                    make_float2(acc[im][in][2], acc[im][in][3]);
            }
        }
    } else {
        int which = bn >> 10;
        int nloc  = bn & 1023;
        unsigned* dst = (which == 0) ? g_Q : (which == 1) ? g_K : g_V;
        #pragma unroll
        for (int im = 0; im < 4; im++) {
            #pragma unroll
            for (int in = 0; in < 4; in++) {
                int r0 = bm + wm + im * 16 + g;      // m = b*2048 + t
                int b  = r0 >> 11, tt = r0 & 2047;
                int n0 = nloc + wn + in * 8 + 2 * t;
                int h  = n0 >> 6, d = n0 & 63;
                size_t base = ((size_t)(b * HH_ + h) * TT_);
                *(uint2*)(dst + (base + tt    ) * DD_ + d) =
                    make_uint2(f2tf(acc[im][in][0]), f2tf(acc[im][in][1]));
                *(uint2*)(dst + (base + tt + 8) * DD_ + d) =
                    make_uint2(f2tf(acc[im][in][2]), f2tf(acc[im][in][3]));
            }
        }
    }
}

// ============================================================================
// Flash attention (causal). Block = 128 q-rows of one (b,h), 8 warps
// (16 q-rows each). K/V streamed in 64-row tiles, 2-stage cp.async.
// Inputs already tf32 bits; output written as tf32 bits to g_Yc.
// ============================================================================
#define AQ_W   (128*68)
#define AP_W   (128*68)
#define AK_W   (64*68)
#define AV_W   (64*72)
#define ATTN_SMEM_WORDS (AQ_W + AP_W + 2*AK_W + 2*AV_W)
#define ATTN_SMEM_BYTES (ATTN_SMEM_WORDS * 4)

__global__ void __launch_bounds__(256) attn_kernel()
{
    extern __shared__ unsigned smem[];
    unsigned* sQ  = smem;                         // [128][68]
    unsigned* sP  = sQ + AQ_W;                    // [128][68]
    unsigned* sK0 = sP + AP_W;                    // [2][64][68]
    unsigned* sV0 = sK0 + 2*AK_W;                 // [2][64][72]
    const unsigned sbase = (unsigned)__cvta_generic_to_shared(smem);
    const unsigned sKa = sbase + (AQ_W + AP_W) * 4;
    const unsigned sVa = sKa + 2*AK_W*4;

    const int bh = blockIdx.y;                    // b*16 + h
    const int qt = gridDim.x - 1 - blockIdx.x;    // biggest tiles first
    const int q0 = qt * 128;
    const int nkt = (q0 >> 6) + 2;                // tiles while kt <= q0+64

    const unsigned* Qp = g_Q + (size_t)bh * TT_ * DD_;
    const unsigned* Kp = g_K + (size_t)bh * TT_ * DD_;
    const unsigned* Vp = g_V + (size_t)bh * TT_ * DD_;

    const int tid = threadIdx.x;
    const int warp = tid >> 5, lane = tid & 31;
    const int g = lane >> 2, t = lane & 3;

    const int lr = tid >> 4;          // 0..15 base row
    const int lc = (tid & 15) * 4;    // col 0..60

    // ---- Q tile (128x64) + KV stage 0, one cp.async group ----
    #pragma unroll
    for (int i = 0; i < 8; i++) {
        int r = lr + i * 16;
        cpa(sbase + (r*68 + lc)*4, Qp + (size_t)(q0 + r)*DD_ + lc);
    }
    #pragma unroll
    for (int i = 0; i < 4; i++) {
        int r = lr + i * 16;
        cpa(sKa + (r*68 + lc)*4, Kp + (size_t)r*DD_ + lc);
        cpa(sVa + (r*72 + lc)*4, Vp + (size_t)r*DD_ + lc);
    }
    CP_COMMIT();

    float m0 = -INFINITY, m1 = -INFINITY;
    float l0 = 0.f, l1 = 0.f;
    float o[8][4];
    #pragma unroll
    for (int i = 0; i < 8; i++)
        #pragma unroll
        for (int r = 0; r < 4; r++) o[i][r] = 0.f;

    const int rq0 = q0 + warp * 16 + g;
    const int rq1 = rq0 + 8;
    const int wrow_min = q0 + warp * 16;

    int cur = 0;
    for (int it = 0; it < nkt; ++it) {
        const int kt = it * 64;
        if (it + 1 < nkt) {
            int nxt = cur ^ 1;
            int kn = kt + 64;
            #pragma unroll
            for (int i = 0; i < 4; i++) {
                int r = lr + i * 16;
                cpa(sKa + (nxt*AK_W + r*68 + lc)*4, Kp + (size_t)(kn + r)*DD_ + lc);
                cpa(sVa + (nxt*AV_W + r*72 + lc)*4, Vp + (size_t)(kn + r)*DD_ + lc);
            }
            CP_COMMIT();
            CP_WAIT1();
        } else {
            CP_WAIT0();
        }
        __syncthreads();

        // warps whose 16 rows are entirely above this k-tile skip it
        if (kt < wrow_min + 16) {
            const unsigned* cK = sK0 + cur*AK_W;
            const unsigned* cV = sV0 + cur*AV_W;

            // ---- S = Q K^T ----
            float s[8][4];
            #pragma unroll
            for (int in = 0; in < 8; in++)
                #pragma unroll
                for (int r = 0; r < 4; r++) s[in][r] = 0.f;

            #pragma unroll
            for (int ks = 0; ks < 64; ks += 8) {
                unsigned a[4];
                int base = warp * 16;
                a[0] = sQ[(base + g    ) * 68 + ks + t    ];
                a[1] = sQ[(base + g + 8) * 68 + ks + t    ];
                a[2] = sQ[(base + g    ) * 68 + ks + t + 4];
                a[3] = sQ[(base + g + 8) * 68 + ks + t + 4];
                #pragma unroll
                for (int in = 0; in < 8; in++) {
                    unsigned b[2];
                    int nb = in * 8 + g;
                    b[0] = cK[nb * 68 + ks + t    ];
                    b[1] = cK[nb * 68 + ks + t + 4];
                    mma8(s[in], a, b);
                }
            }

            // ---- scale + causal mask + row max ----
            const bool needmask = (kt + 63 > wrow_min);
            float mx0 = -INFINITY, mx1 = -INFINITY;
            #pragma unroll
            for (int in = 0; in < 8; in++) {
                int c = kt + in * 8 + 2 * t;
                float x0 = s[in][0] * SOFTMAX_SCL;
                float x1 = s[in][1] * SOFTMAX_SCL;
                float x2 = s[in][2] * SOFTMAX_SCL;
                float x3 = s[in][3] * SOFTMAX_SCL;
                if (needmask) {
                    if (c     > rq0) x0 = -INFINITY;
                    if (c + 1 > rq0) x1 = -INFINITY;
                    if (c     > rq1) x2 = -INFINITY;
                    if (c + 1 > rq1) x3 = -INFINITY;
                }
                s[in][0] = x0; s[in][1] = x1; s[in][2] = x2; s[in][3] = x3;
                mx0 = fmaxf(mx0, fmaxf(x0, x1));
                mx1 = fmaxf(mx1, fmaxf(x2, x3));
            }
            mx0 = fmaxf(mx0, __shfl_xor_sync(0xffffffffu, mx0, 1));
            mx0 = fmaxf(mx0, __shfl_xor_sync(0xffffffffu, mx0, 2));
            mx1 = fmaxf(mx1, __shfl_xor_sync(0xffffffffu, mx1, 1));
            mx1 = fmaxf(mx1, __shfl_xor_sync(0xffffffffu, mx1, 2));

            float nm0 = fmaxf(m0, mx0), nm1 = fmaxf(m1, mx1);
            float cor0 = ex2(m0 - nm0), cor1 = ex2(m1 - nm1);
            m0 = nm0; m1 = nm1;

            // ---- P = 2^(x-m), sums, stage tf32 P ----
            float sum0 = 0.f, sum1 = 0.f;
            #pragma unroll
            for (int in = 0; in < 8; in++) {
                float p0 = ex2(s[in][0] - nm0);
                float p1 = ex2(s[in][1] - nm0);
                float p2 = ex2(s[in][2] - nm1);
                float p3 = ex2(s[in][3] - nm1);
                sum0 += p0 + p1;
                sum1 += p2 + p3;
                int cl = in * 8 + 2 * t;
                int r0l = warp * 16 + g;
                sP[ r0l      * 68 + cl    ] = f2tf(p0);
                sP[ r0l      * 68 + cl + 1] = f2tf(p1);
                sP[(r0l + 8) * 68 + cl    ] = f2tf(p2);
                sP[(r0l + 8) * 68 + cl + 1] = f2tf(p3);
            }
            sum0 += __shfl_xor_sync(0xffffffffu, sum0, 1);
            sum0 += __shfl_xor_sync(0xffffffffu, sum0, 2);
            sum1 += __shfl_xor_sync(0xffffffffu, sum1, 1);
            sum1 += __shfl_xor_sync(0xffffffffu, sum1, 2);
            l0 = l0 * cor0 + sum0;
            l1 = l1 * cor1 + sum1;

            #pragma unroll
            for (int in = 0; in < 8; in++) {
                o[in][0] *= cor0; o[in][1] *= cor0;
                o[in][2] *= cor1; o[in][3] *= cor1;
            }
            __syncwarp();   // sP rows are warp-private

            // ---- O += P V ----
            #pragma unroll
            for (int ks = 0; ks < 64; ks += 8) {
                unsigned a[4];
                int base = warp * 16;
                a[0] = sP[(base + g    ) * 68 + ks + t    ];
                a[1] = sP[(base + g + 8) * 68 + ks + t    ];
                a[2] = sP[(base + g    ) * 68 + ks + t + 4];
                a[3] = sP[(base + g + 8) * 68 + ks + t + 4];
                #pragma unroll
                for (int in = 0; in < 8; in++) {
                    unsigned b[2];
                    b[0] = cV[(ks + t    ) * 72 + in * 8 + g];
                    b[1] = cV[(ks + t + 4) * 72 + in * 8 + g];
                    mma8(o[in], a, b);
                }
            }
            __syncwarp();
        }
        __syncthreads();
        cur ^= 1;
    }

    // ---- normalize, write tf32 merged-head output ----
    const float inv0 = 1.f / l0, inv1 = 1.f / l1;
    const int b = bh >> 4, h = bh & 15;
    #pragma unroll
    for (int in = 0; in < 8; in++) {
        int dcol = in * 8 + 2 * t;
        int r0 = q0 + warp * 16 + g;
        size_t base0 = ((size_t)(b * TT_ + r0)     * CC_) + h * DD_ + dcol;
        size_t base1 = ((size_t)(b * TT_ + r0 + 8) * CC_) + h * DD_ + dcol;
        *(uint2*)(g_Yc + base0) =
            make_uint2(f2tf(o[in][0] * inv0), f2tf(o[in][1] * inv0));
        *(uint2*)(g_Yc + base1) =
            make_uint2(f2tf(o[in][2] * inv1), f2tf(o[in][3] * inv1));
    }
}

// ============================================================================
// launch
// ============================================================================
extern "C" void kernel_launch(void* const* d_in, const int* in_sizes, int n_in,
                              void* d_out, int out_size)
{
    const float* X  = (const float*)d_in[0];
    const float* Wq = (const float*)d_in[1];
    const float* Wk = (const float*)d_in[2];
    const float* Wv = (const float*)d_in[3];
    const float* Wo = (const float*)d_in[4];
    float* out = (float*)d_out;

    static int attr_done = 0;
    cudaFuncSetAttribute(gemm_nt<1>, cudaFuncAttributeMaxDynamicSharedMemorySize,
                         GEMM_SMEM_BYTES);
    cudaFuncSetAttribute(gemm_nt<0>, cudaFuncAttributeMaxDynamicSharedMemorySize,
                         GEMM_SMEM_BYTES);
    cudaFuncSetAttribute(attn_kernel, cudaFuncAttributeMaxDynamicSharedMemorySize,
                         ATTN_SMEM_BYTES);
    (void)attr_done;

    // 0) tf32 pre-conversion (X: 1M float4, weights: 4*256K float4)
    conv_kernel<<<8192, 256>>>((const float4*)X, (const float4*)Wq,
                               (const float4*)Wk, (const float4*)Wv,
                               (const float4*)Wo);

    // 1) QKV: M=4096, N=3072, K=1024
    unsigned* Xt = nullptr, *Wt = nullptr;
    cudaGetSymbolAddress((void**)&Xt, g_Xt);
    cudaGetSymbolAddress((void**)&Wt, g_Wt);
    unsigned* Yc = nullptr;
    cudaGetSymbolAddress((void**)&Yc, g_Yc);

    gemm_nt<1><<<dim3(24, 32), 256, GEMM_SMEM_BYTES>>>(Xt, Wt, nullptr);

    // 2) attention: grid = (q-tiles=16, b*h=32)
    attn_kernel<<<dim3(16, 32), 256, ATTN_SMEM_BYTES>>>();

    // 3) output projection: M=4096, N=1024, K=1024
    gemm_nt<0><<<dim3(8, 32), 256, GEMM_SMEM_BYTES>>>(Yc, Wt + 3*1024*1024, out);
}

// round 4
// speedup vs baseline: 1.8194x; 1.8194x over previous
#include <cuda_runtime.h>
#include <cuda_fp16.h>
#include <cstdint>
#include <cstdio>

// ---------------- problem constants ----------------
#define BB_ 2
#define TT_ 2048
#define CC_ 1024
#define HH_ 16
#define DD_ 64

// exp(s/8) = 2^(s * log2(e)/8)
#define SOFTMAX_SCL 0.18033688011112042f

// ---------------- scratch: fp16 stored as unsigned (half2 units) ----------------
__device__ __align__(16) unsigned g_Xt[BB_*TT_*CC_/2];      // X fp16 [m][k]
__device__ __align__(16) unsigned g_Wt[4*CC_*CC_/2];        // Wq|Wk|Wv|Wo fp16 [n][k]
__device__ __align__(16) unsigned g_Q [BB_*HH_*TT_*DD_/2];  // [b,h,t,d]
__device__ __align__(16) unsigned g_K [BB_*HH_*TT_*DD_/2];  // [b,h,t,d]
__device__ __align__(16) unsigned g_Vt[BB_*HH_*TT_*DD_/2];  // TRANSPOSED [b,h,d,t]
__device__ __align__(16) unsigned g_Yc[BB_*TT_*CC_/2];      // merged heads [b,t,c]

// ---------------- helpers ----------------
__device__ __forceinline__ float ex2(float x) {
    float y;
    asm("ex2.approx.f32 %0, %1;" : "=f"(y) : "f"(x));
    return y;
}
__device__ __forceinline__ unsigned packh2(float a, float b) {
    __half2 h = __floats2half2_rn(a, b);
    return *(unsigned*)&h;
}
__device__ __forceinline__ void mma16(float* d, const unsigned* a, const unsigned* b) {
    asm volatile(
        "mma.sync.aligned.m16n8k16.row.col.f32.f16.f16.f32 "
        "{%0,%1,%2,%3},{%4,%5,%6,%7},{%8,%9},{%0,%1,%2,%3};"
        : "+f"(d[0]), "+f"(d[1]), "+f"(d[2]), "+f"(d[3])
        : "r"(a[0]), "r"(a[1]), "r"(a[2]), "r"(a[3]),
          "r"(b[0]), "r"(b[1]));
}
__device__ __forceinline__ void cpa(unsigned dst, const void* src) {
    asm volatile("cp.async.cg.shared.global [%0], [%1], 16;" :: "r"(dst), "l"(src));
}
#define CP_COMMIT() asm volatile("cp.async.commit_group;")
#define CP_WAIT1()  asm volatile("cp.async.wait_group 1;")
#define CP_WAIT0()  asm volatile("cp.async.wait_group 0;")
__device__ __forceinline__ unsigned smem_u32(const void* p) {
    return (unsigned)__cvta_generic_to_shared(p);
}

// ============================================================================
// one-shot fp16 conversion: X (1M float4) + 4 weights (256K float4 each)
// ============================================================================
__global__ void __launch_bounds__(256) conv_kernel(
    const float4* __restrict__ X,  const float4* __restrict__ Wq,
    const float4* __restrict__ Wk, const float4* __restrict__ Wv,
    const float4* __restrict__ Wo)
{
    int i = blockIdx.x * 256 + threadIdx.x;          // 0 .. 2M-1
    const float4* src;
    uint2* dst;
    if (i < (1 << 20)) {
        src = X + i;
        dst = (uint2*)g_Xt + i;
    } else {
        int j = i - (1 << 20);
        int w = j >> 18, r = j & 0x3FFFF;
        const float4* s4 = (w == 0) ? Wq : (w == 1) ? Wk : (w == 2) ? Wv : Wo;
        src = s4 + r;
        dst = (uint2*)g_Wt + (w << 18) + r;
    }
    float4 v = *src;
    *dst = make_uint2(packh2(v.x, v.y), packh2(v.z, v.w));
}

// ============================================================================
// fp16 GEMM: C[m,n] = sum_k A[m,k]*B[n,k]  (NT), K=1024.
// 128x128 CTA tile, 8 warps (2x4), warp tile 64x32, m16n8k16 mma.
// k-chunk 64 halves, 2-stage cp.async double buffering.
// SMEM rows padded to 72 halves (36 half2 units -> 36%32==4, conflict-free).
// MODE 1: epilogue -> g_Q/g_K (as [b,h,t,d]) or g_Vt (TRANSPOSED [b,h,d,t]).
// MODE 0: A=g_Yc, writes fp32 Cout.
// ============================================================================
#define G_ROW_B 144            // bytes per padded smem row (72 halves)
#define G_ROW_U 36             // half2 units per row
#define G_AB_B  18432          // one matrix block (128 rows * 144 B)
#define G_STG_B 36864          // A+B per stage
#define G_STG_U 9216           // in half2 units
#define G_B_U   4608           // B offset within stage, units
#define GEMM_SMEM_BYTES (2*G_STG_B)

template<int MODE>
__global__ void __launch_bounds__(256, 2) gemm_fp16(
    const __half* __restrict__ A,
    const __half* __restrict__ B,
    float* __restrict__ Cout)
{
    extern __shared__ unsigned smem[];
    const unsigned sbase = smem_u32(smem);

    const int tid  = threadIdx.x;
    const int bm   = blockIdx.y * 128;
    const int bn   = blockIdx.x * 128;
    const int warp = tid >> 5, lane = tid & 31;
    const int g = lane >> 2, t = lane & 3;
    const int wm = (warp & 1) * 64;
    const int wn = (warp >> 1) * 32;

    const __half* Ap = A + (size_t)bm * 1024;
    const __half* Bp = B + (size_t)bn * 1024;

    const int lr = tid >> 3;           // 0..31 base row
    const int cc = tid & 7;            // 16B chunk (8 halves)

    float acc[4][4][4];
    #pragma unroll
    for (int i = 0; i < 4; i++)
        #pragma unroll
        for (int j = 0; j < 4; j++)
            #pragma unroll
            for (int r = 0; r < 4; r++) acc[i][j][r] = 0.f;

    auto load_stage = [&](int s, int k0) {
        const unsigned stA = sbase + (unsigned)s * G_STG_B;
        const unsigned stB = stA + G_AB_B;
        #pragma unroll
        for (int i = 0; i < 4; i++) {
            int r = lr + i * 32;
            cpa(stA + (unsigned)r * G_ROW_B + (unsigned)cc * 16,
                Ap + (size_t)r * 1024 + k0 + cc * 8);
            cpa(stB + (unsigned)r * G_ROW_B + (unsigned)cc * 16,
                Bp + (size_t)r * 1024 + k0 + cc * 8);
        }
    };

    load_stage(0, 0);
    CP_COMMIT();

    #pragma unroll 1
    for (int i = 0; i < 16; ++i) {            // 16 chunks of 64 halves
        const int s = i & 1;
        if (i + 1 < 16) {
            load_stage(s ^ 1, (i + 1) * 64);
            CP_COMMIT();
            CP_WAIT1();
        } else {
            CP_WAIT0();
        }
        __syncthreads();

        const unsigned* cA = smem + (size_t)s * G_STG_U;
        const unsigned* cB = cA + G_B_U;
        #pragma unroll
        for (int ksu = 0; ksu < 32; ksu += 8) {   // 4 mma k-steps (k=16 halves)
            unsigned afr[4][4], bfr[4][2];
            #pragma unroll
            for (int im = 0; im < 4; im++) {
                int base = wm + im * 16;
                afr[im][0] = cA[(base + g    ) * G_ROW_U + ksu + t    ];
                afr[im][1] = cA[(base + g + 8) * G_ROW_U + ksu + t    ];
                afr[im][2] = cA[(base + g    ) * G_ROW_U + ksu + t + 4];
                afr[im][3] = cA[(base + g + 8) * G_ROW_U + ksu + t + 4];
            }
            #pragma unroll
            for (int in = 0; in < 4; in++) {
                int nb = wn + in * 8 + g;
                bfr[in][0] = cB[nb * G_ROW_U + ksu + t    ];
                bfr[in][1] = cB[nb * G_ROW_U + ksu + t + 4];
            }
            #pragma unroll
            for (int im = 0; im < 4; im++)
                #pragma unroll
                for (int in = 0; in < 4; in++)
                    mma16(acc[im][in], afr[im], bfr[in]);
        }
        __syncthreads();
    }

    // ---------------- epilogue ----------------
    if (MODE == 0) {
        #pragma unroll
        for (int im = 0; im < 4; im++) {
            #pragma unroll
            for (int in = 0; in < 4; in++) {
                int r0 = bm + wm + im * 16 + g;
                int c0 = bn + wn + in * 8 + 2 * t;
                *(float2*)(Cout + (size_t)r0 * 1024 + c0) =
                    make_float2(acc[im][in][0], acc[im][in][1]);
                *(float2*)(Cout + (size_t)(r0 + 8) * 1024 + c0) =
                    make_float2(acc[im][in][2], acc[im][in][3]);
            }
        }
    } else {
        const int which = bn >> 10;
        const int nloc  = bn & 1023;
        #pragma unroll
        for (int im = 0; im < 4; im++) {
            #pragma unroll
            for (int in = 0; in < 4; in++) {
                int r0 = bm + wm + im * 16 + g;      // m = b*2048 + t
                int b  = r0 >> 11, tt = r0 & 2047;
                int n0 = nloc + wn + in * 8 + 2 * t;
                int h  = n0 >> 6, d = n0 & 63;
                if (which < 2) {
                    unsigned* dst = (which == 0) ? g_Q : g_K;
                    size_t base = ((size_t)(b * HH_ + h) * TT_ + tt) * (DD_/2) + (d >> 1);
                    dst[base] = packh2(acc[im][in][0], acc[im][in][1]);
                    dst[base + 8 * (DD_/2)] = packh2(acc[im][in][2], acc[im][in][3]);
                } else {
                    // V transposed: [b,h,d,t]
                    __half* dv = (__half*)g_Vt;
                    size_t bb = ((size_t)(b * HH_ + h) * DD_ + d) * TT_ + tt;
                    dv[bb         ] = __float2half_rn(acc[im][in][0]);
                    dv[bb + TT_   ] = __float2half_rn(acc[im][in][1]);
                    dv[bb + 8     ] = __float2half_rn(acc[im][in][2]);
                    dv[bb + TT_+8 ] = __float2half_rn(acc[im][in][3]);
                }
            }
        }
    }
}

// ============================================================================
// Flash attention (causal), fp16 mma. Block = 128 q-rows of one (b,h),
// 8 warps (16 q-rows each). K / V^T streamed in 64-wide tiles, 2-stage cp.async.
// ============================================================================
// smem (half2 units): sQ[128][36] @0, sP[128][36] @4608,
//                     sK[2][64][36] @9216, sVt[2][64][36] @13824
#define A_SP_U  4608
#define A_SK_U  9216
#define A_SV_U  13824
#define A_STG_U 2304
#define A_SK_B  36864
#define A_SV_B  55296
#define A_STG_B 9216
#define ATTN_SMEM_BYTES 73728

__global__ void __launch_bounds__(256) attn_kernel()
{
    extern __shared__ unsigned smem[];
    const unsigned sbase = smem_u32(smem);

    const int bh = blockIdx.y;                    // b*16 + h
    const int qt = gridDim.x - 1 - blockIdx.x;    // biggest tiles first
    const int q0 = qt * 128;
    const int nkt = (q0 >> 6) + 2;

    const __half* Qp  = (const __half*)g_Q  + (size_t)bh * TT_ * DD_;
    const __half* Kp  = (const __half*)g_K  + (size_t)bh * TT_ * DD_;
    const __half* Vtp = (const __half*)g_Vt + (size_t)bh * DD_ * TT_;

    const int tid = threadIdx.x;
    const int warp = tid >> 5, lane = tid & 31;
    const int g = lane >> 2, t = lane & 3;

    const int lr = tid >> 3;          // 0..31 base row
    const int cc = tid & 7;           // 16B chunk

    // ---- Q tile (128 rows x 64 halves) + KV stage 0 ----
    #pragma unroll
    for (int i = 0; i < 4; i++) {
        int r = lr + i * 32;
        cpa(sbase + (unsigned)r * 144 + (unsigned)cc * 16,
            Qp + (size_t)(q0 + r) * DD_ + cc * 8);
    }
    #pragma unroll
    for (int i = 0; i < 2; i++) {
        int r = lr + i * 32;          // K row (kv) / Vt row (d)
        cpa(sbase + A_SK_B + (unsigned)r * 144 + (unsigned)cc * 16,
            Kp + (size_t)r * DD_ + cc * 8);
        cpa(sbase + A_SV_B + (unsigned)r * 144 + (unsigned)cc * 16,
            Vtp + (size_t)r * TT_ + cc * 8);
    }
    CP_COMMIT();

    float m0 = -INFINITY, m1 = -INFINITY;
    float l0 = 0.f, l1 = 0.f;
    float o[8][4];
    #pragma unroll
    for (int i = 0; i < 8; i++)
        #pragma unroll
        for (int r = 0; r < 4; r++) o[i][r] = 0.f;

    const int rq0 = q0 + warp * 16 + g;
    const int rq1 = rq0 + 8;
    const int wrow_min = q0 + warp * 16;

    for (int it = 0; it < nkt; ++it) {
        const int kt = it * 64;
        const int s = it & 1;
        if (it + 1 < nkt) {
            int ns = s ^ 1;
            int kn = kt + 64;
            #pragma unroll
            for (int i = 0; i < 2; i++) {
                int r = lr + i * 32;
                cpa(sbase + A_SK_B + (unsigned)ns * A_STG_B + (unsigned)r * 144 + (unsigned)cc * 16,
                    Kp + (size_t)(kn + r) * DD_ + cc * 8);
                cpa(sbase + A_SV_B + (unsigned)ns * A_STG_B + (unsigned)r * 144 + (unsigned)cc * 16,
                    Vtp + (size_t)r * TT_ + kn + cc * 8);
            }
            CP_COMMIT();
            CP_WAIT1();
        } else {
            CP_WAIT0();
        }
        __syncthreads();

        if (kt < wrow_min + 16) {
            const unsigned* cK = smem + A_SK_U + (size_t)s * A_STG_U;
            const unsigned* cV = smem + A_SV_U + (size_t)s * A_STG_U;
            unsigned* sP = smem + A_SP_U;

            // ---- S = Q K^T : k-dim = 64 halves (d), 4 mma steps ----
            float sreg[8][4];
            #pragma unroll
            for (int in = 0; in < 8; in++)
                #pragma unroll
                for (int r = 0; r < 4; r++) sreg[in][r] = 0.f;

            #pragma unroll
            for (int ksu = 0; ksu < 32; ksu += 8) {
                unsigned a[4];
                int base = warp * 16;
                a[0] = smem[(base + g    ) * 36 + ksu + t    ];
                a[1] = smem[(base + g + 8) * 36 + ksu + t    ];
                a[2] = smem[(base + g    ) * 36 + ksu + t + 4];
                a[3] = smem[(base + g + 8) * 36 + ksu + t + 4];
                #pragma unroll
                for (int in = 0; in < 8; in++) {
                    unsigned b[2];
                    int nb = in * 8 + g;
                    b[0] = cK[nb * 36 + ksu + t    ];
                    b[1] = cK[nb * 36 + ksu + t + 4];
                    mma16(sreg[in], a, b);
                }
            }

            // ---- scale + causal mask + row max ----
            const bool needmask = (kt + 63 > wrow_min);
            float mx0 = -INFINITY, mx1 = -INFINITY;
            #pragma unroll
            for (int in = 0; in < 8; in++) {
                int c = kt + in * 8 + 2 * t;
                float x0 = sreg[in][0] * SOFTMAX_SCL;
                float x1 = sreg[in][1] * SOFTMAX_SCL;
                float x2 = sreg[in][2] * SOFTMAX_SCL;
                float x3 = sreg[in][3] * SOFTMAX_SCL;
                if (needmask) {
                    if (c     > rq0) x0 = -INFINITY;
                    if (c + 1 > rq0) x1 = -INFINITY;
                    if (c     > rq1) x2 = -INFINITY;
                    if (c + 1 > rq1) x3 = -INFINITY;
                }
                sreg[in][0] = x0; sreg[in][1] = x1;
                sreg[in][2] = x2; sreg[in][3] = x3;
                mx0 = fmaxf(mx0, fmaxf(x0, x1));
                mx1 = fmaxf(mx1, fmaxf(x2, x3));
            }
            mx0 = fmaxf(mx0, __shfl_xor_sync(0xffffffffu, mx0, 1));
            mx0 = fmaxf(mx0, __shfl_xor_sync(0xffffffffu, mx0, 2));
            mx1 = fmaxf(mx1, __shfl_xor_sync(0xffffffffu, mx1, 1));
            mx1 = fmaxf(mx1, __shfl_xor_sync(0xffffffffu, mx1, 2));

            float nm0 = fmaxf(m0, mx0), nm1 = fmaxf(m1, mx1);
            float cor0 = ex2(m0 - nm0), cor1 = ex2(m1 - nm1);
            m0 = nm0; m1 = nm1;

            // ---- P = 2^(x-m), sums, stage P as half2 ----
            float sum0 = 0.f, sum1 = 0.f;
            #pragma unroll
            for (int in = 0; in < 8; in++) {
                float p0 = ex2(sreg[in][0] - nm0);
                float p1 = ex2(sreg[in][1] - nm0);
                float p2 = ex2(sreg[in][2] - nm1);
                float p3 = ex2(sreg[in][3] - nm1);
                sum0 += p0 + p1;
                sum1 += p2 + p3;
                int cu = in * 4 + t;
                int r0l = warp * 16 + g;
                sP[ r0l      * 36 + cu] = packh2(p0, p1);
                sP[(r0l + 8) * 36 + cu] = packh2(p2, p3);
            }
            sum0 += __shfl_xor_sync(0xffffffffu, sum0, 1);
            sum0 += __shfl_xor_sync(0xffffffffu, sum0, 2);
            sum1 += __shfl_xor_sync(0xffffffffu, sum1, 1);
            sum1 += __shfl_xor_sync(0xffffffffu, sum1, 2);
            l0 = l0 * cor0 + sum0;
            l1 = l1 * cor1 + sum1;

            #pragma unroll
            for (int in = 0; in < 8; in++) {
                o[in][0] *= cor0; o[in][1] *= cor0;
                o[in][2] *= cor1; o[in][3] *= cor1;
            }
            __syncwarp();   // sP rows are warp-private

            // ---- O += P V : k-dim = 64 kv, 4 mma steps ----
            #pragma unroll
            for (int ksu = 0; ksu < 32; ksu += 8) {
                unsigned a[4];
                int base = warp * 16;
                a[0] = sP[(base + g    ) * 36 + ksu + t    ];
                a[1] = sP[(base + g + 8) * 36 + ksu + t    ];
                a[2] = sP[(base + g    ) * 36 + ksu + t + 4];
                a[3] = sP[(base + g + 8) * 36 + ksu + t + 4];
                #pragma unroll
                for (int in = 0; in < 8; in++) {
                    unsigned b[2];
                    int nb = in * 8 + g;      // d index
                    b[0] = cV[nb * 36 + ksu + t    ];
                    b[1] = cV[nb * 36 + ksu + t + 4];
                    mma16(o[in], a, b);
                }
            }
            __syncwarp();
        }
        __syncthreads();
    }

    // ---- normalize, write half2 merged-head output ----
    const float inv0 = 1.f / l0, inv1 = 1.f / l1;
    const int b = bh >> 4, h = bh & 15;
    #pragma unroll
    for (int in = 0; in < 8; in++) {
        int cu = in * 4 + t;                   // half2 unit within head
        int r0 = q0 + warp * 16 + g;
        size_t base0 = ((size_t)(b * TT_ + r0)     * (CC_/2)) + h * (DD_/2) + cu;
        size_t base1 = ((size_t)(b * TT_ + r0 + 8) * (CC_/2)) + h * (DD_/2) + cu;
        g_Yc[base0] = packh2(o[in][0] * inv0, o[in][1] * inv0);
        g_Yc[base1] = packh2(o[in][2] * inv1, o[in][3] * inv1);
    }
}

// ============================================================================
// launch
// ============================================================================
extern "C" void kernel_launch(void* const* d_in, const int* in_sizes, int n_in,
                              void* d_out, int out_size)
{
    const float* X  = (const float*)d_in[0];
    const float* Wq = (const float*)d_in[1];
    const float* Wk = (const float*)d_in[2];
    const float* Wv = (const float*)d_in[3];
    const float* Wo = (const float*)d_in[4];
    float* out = (float*)d_out;

    cudaFuncSetAttribute(gemm_fp16<1>, cudaFuncAttributeMaxDynamicSharedMemorySize,
                         GEMM_SMEM_BYTES);
    cudaFuncSetAttribute(gemm_fp16<0>, cudaFuncAttributeMaxDynamicSharedMemorySize,
                         GEMM_SMEM_BYTES);
    cudaFuncSetAttribute(attn_kernel, cudaFuncAttributeMaxDynamicSharedMemorySize,
                         ATTN_SMEM_BYTES);

    unsigned *Xt = nullptr, *Wt = nullptr, *Yc = nullptr;
    cudaGetSymbolAddress((void**)&Xt, g_Xt);
    cudaGetSymbolAddress((void**)&Wt, g_Wt);
    cudaGetSymbolAddress((void**)&Yc, g_Yc);

    // 0) fp16 pre-conversion
    conv_kernel<<<8192, 256>>>((const float4*)X, (const float4*)Wq,
                               (const float4*)Wk, (const float4*)Wv,
                               (const float4*)Wo);

    // 1) QKV: M=4096, N=3072 (24 tiles), K=1024
    gemm_fp16<1><<<dim3(24, 32), 256, GEMM_SMEM_BYTES>>>(
        (const __half*)Xt, (const __half*)Wt, nullptr);

    // 2) attention: grid = (q-tiles=16, b*h=32)
    attn_kernel<<<dim3(16, 32), 256, ATTN_SMEM_BYTES>>>();

    // 3) output projection: M=4096, N=1024, K=1024
    gemm_fp16<0><<<dim3(8, 32), 256, GEMM_SMEM_BYTES>>>(
        (const __half*)Yc, (const __half*)Wt + 3*1024*1024, out);
}

// round 6
// speedup vs baseline: 1.9065x; 1.0479x over previous
#include <cuda_runtime.h>
#include <cuda_fp16.h>
#include <cstdint>
#include <cstdio>

// ---------------- problem constants ----------------
#define BB_ 2
#define TT_ 2048
#define CC_ 1024
#define HH_ 16
#define DD_ 64

// exp(s/8) = 2^(s * log2(e)/8)
#define SOFTMAX_SCL 0.18033688011112042f

// ---------------- scratch: fp16 stored as unsigned (half2 units) ----------------
__device__ __align__(16) unsigned g_Xt[BB_*TT_*CC_/2];      // X fp16 [m][k]
__device__ __align__(16) unsigned g_Wt[4*CC_*CC_/2];        // Wq|Wk|Wv|Wo fp16 [n][k]
__device__ __align__(16) unsigned g_Q [BB_*HH_*TT_*DD_/2];  // [b,h,t,d]
__device__ __align__(16) unsigned g_K [BB_*HH_*TT_*DD_/2];  // [b,h,t,d]
__device__ __align__(16) unsigned g_Vt[BB_*HH_*TT_*DD_/2];  // TRANSPOSED [b,h,d,t]
__device__ __align__(16) unsigned g_Yc[BB_*TT_*CC_/2];      // merged heads [b,t,c]

// ---------------- helpers ----------------
__device__ __forceinline__ float ex2(float x) {
    float y;
    asm("ex2.approx.f32 %0, %1;" : "=f"(y) : "f"(x));
    return y;
}
__device__ __forceinline__ unsigned packh2(float a, float b) {
    __half2 h = __floats2half2_rn(a, b);
    return *(unsigned*)&h;
}
__device__ __forceinline__ void mma16(float* d, const unsigned* a, const unsigned* b) {
    asm volatile(
        "mma.sync.aligned.m16n8k16.row.col.f32.f16.f16.f32 "
        "{%0,%1,%2,%3},{%4,%5,%6,%7},{%8,%9},{%0,%1,%2,%3};"
        : "+f"(d[0]), "+f"(d[1]), "+f"(d[2]), "+f"(d[3])
        : "r"(a[0]), "r"(a[1]), "r"(a[2]), "r"(a[3]),
          "r"(b[0]), "r"(b[1]));
}
__device__ __forceinline__ void ldsm4(unsigned* r, unsigned addr) {
    asm volatile("ldmatrix.sync.aligned.m8n8.x4.shared.b16 {%0,%1,%2,%3}, [%4];"
        : "=r"(r[0]), "=r"(r[1]), "=r"(r[2]), "=r"(r[3]) : "r"(addr));
}
__device__ __forceinline__ void cpa(unsigned dst, const void* src) {
    asm volatile("cp.async.cg.shared.global [%0], [%1], 16;" :: "r"(dst), "l"(src));
}
#define CP_COMMIT() asm volatile("cp.async.commit_group;")
#define CP_WAIT1()  asm volatile("cp.async.wait_group 1;")
#define CP_WAIT0()  asm volatile("cp.async.wait_group 0;")
__device__ __forceinline__ unsigned smem_u32(const void* p) {
    return (unsigned)__cvta_generic_to_shared(p);
}

// ============================================================================
// one-shot fp16 conversion: X (1M float4) + 4 weights (256K float4 each)
// ============================================================================
__global__ void __launch_bounds__(256) conv_kernel(
    const float4* __restrict__ X,  const float4* __restrict__ Wq,
    const float4* __restrict__ Wk, const float4* __restrict__ Wv,
    const float4* __restrict__ Wo)
{
    int i = blockIdx.x * 256 + threadIdx.x;          // 0 .. 2M-1
    const float4* src;
    uint2* dst;
    if (i < (1 << 20)) {
        src = X + i;
        dst = (uint2*)g_Xt + i;
    } else {
        int j = i - (1 << 20);
        int w = j >> 18, r = j & 0x3FFFF;
        const float4* s4 = (w == 0) ? Wq : (w == 1) ? Wk : (w == 2) ? Wv : Wo;
        src = s4 + r;
        dst = (uint2*)g_Wt + (w << 18) + r;
    }
    float4 v = *src;
    *dst = make_uint2(packh2(v.x, v.y), packh2(v.z, v.w));
}

// ============================================================================
// fp16 GEMM: C[m,n] = sum_k A[m,k]*B[n,k]  (NT), K=1024.
// CTA 128x256, 8 warps (2m x 4n), warp tile 64x64, m16n8k16 + ldmatrix.x4.
// k-chunk 64 halves, 2-stage cp.async.
// SMEM rows: 72 halves = 144B (rows hop 4 banks -> LDSM conflict-free).
// MODE 1: epilogue -> g_Q/g_K ([b,h,t,d]) or g_Vt ([b,h,d,t]).
// MODE 0: A=g_Yc, writes fp32 Cout.
// ============================================================================
#define G_ROW_B 144u
#define G_A_B   18432u          // A block bytes (128*144)
#define G_STG_B 55296u          // A+B per stage (128*144 + 256*144)
#define GEMM_SMEM_BYTES (2*55296)

template<int MODE>
__global__ void __launch_bounds__(256, 1) gemm_fp16(
    const __half* __restrict__ A,
    const __half* __restrict__ B,
    float* __restrict__ Cout)
{
    extern __shared__ unsigned smem[];
    const unsigned sbase = smem_u32(smem);

    const int tid  = threadIdx.x;
    const int bm   = blockIdx.y * 128;
    const int bn   = blockIdx.x * 256;
    const int warp = tid >> 5, lane = tid & 31;
    const int g = lane >> 2, t = lane & 3;
    const int wm = (warp & 1) * 64;          // warp m offset
    const int wn = (warp >> 1) * 64;         // warp n offset

    const __half* Ap = A + (size_t)bm * 1024;
    const __half* Bp = B + (size_t)bn * 1024;

    float acc[4][8][4];
    #pragma unroll
    for (int i = 0; i < 4; i++)
        #pragma unroll
        for (int j = 0; j < 8; j++)
            #pragma unroll
            for (int r = 0; r < 4; r++) acc[i][j][r] = 0.f;

    // ldmatrix per-lane relative byte offsets
    unsigned aRel[4], bRel[4];
    {
        int rA = (lane & 15), kA = (lane >> 4) * 8;
        #pragma unroll
        for (int im = 0; im < 4; im++)
            aRel[im] = (unsigned)((wm + im * 16 + rA) * 72 + kA) * 2u;
        int rB = ((lane >> 4) & 1) * 8 + (lane & 7);
        int kB = ((lane >> 3) & 1) * 8;
        #pragma unroll
        for (int j = 0; j < 4; j++)
            bRel[j] = G_A_B + (unsigned)((wn + j * 16 + rB) * 72 + kB) * 2u;
    }

    auto load_stage = [&](int s, int k0) {
        const unsigned st = sbase + (unsigned)s * G_STG_B;
        #pragma unroll
        for (int i = 0; i < 4; i++) {                       // A: 1024 chunks
            int id = tid + (i << 8);
            int r = id >> 3, c = id & 7;
            cpa(st + (unsigned)r * G_ROW_B + (unsigned)c * 16u,
                Ap + (size_t)r * 1024 + k0 + c * 8);
        }
        #pragma unroll
        for (int i = 0; i < 8; i++) {                       // B: 2048 chunks
            int id = tid + (i << 8);
            int r = id >> 3, c = id & 7;
            cpa(st + G_A_B + (unsigned)r * G_ROW_B + (unsigned)c * 16u,
                Bp + (size_t)r * 1024 + k0 + c * 8);
        }
    };

    load_stage(0, 0);
    CP_COMMIT();

    #pragma unroll 1
    for (int i = 0; i < 16; ++i) {
        const int s = i & 1;
        if (i + 1 < 16) {
            load_stage(s ^ 1, (i + 1) * 64);
            CP_COMMIT();
            CP_WAIT1();
        } else {
            CP_WAIT0();
        }
        __syncthreads();

        const unsigned stg = sbase + (unsigned)s * G_STG_B;
        #pragma unroll
        for (int ks8 = 0; ks8 < 4; ks8++) {                 // 4 k-steps of 16
            const unsigned ko = (unsigned)ks8 * 32u;        // 16 halves = 32B
            unsigned afr[4][4], bfr[8][2];
            #pragma unroll
            for (int im = 0; im < 4; im++)
                ldsm4(afr[im], stg + aRel[im] + ko);
            #pragma unroll
            for (int j = 0; j < 4; j++)
                ldsm4(&bfr[2*j][0], stg + bRel[j] + ko);
            #pragma unroll
            for (int im = 0; im < 4; im++)
                #pragma unroll
                for (int in = 0; in < 8; in++)
                    mma16(acc[im][in], afr[im], bfr[in]);
        }
        __syncthreads();
    }

    // ---------------- epilogue ----------------
    if (MODE == 0) {
        #pragma unroll
        for (int im = 0; im < 4; im++) {
            #pragma unroll
            for (int in = 0; in < 8; in++) {
                int r0 = bm + wm + im * 16 + g;
                int c0 = bn + wn + in * 8 + 2 * t;
                *(float2*)(Cout + (size_t)r0 * 1024 + c0) =
                    make_float2(acc[im][in][0], acc[im][in][1]);
                *(float2*)(Cout + (size_t)(r0 + 8) * 1024 + c0) =
                    make_float2(acc[im][in][2], acc[im][in][3]);
            }
        }
    } else {
        const int which = bn >> 10;
        const int nloc  = bn & 1023;
        #pragma unroll
        for (int im = 0; im < 4; im++) {
            #pragma unroll
            for (int in = 0; in < 8; in++) {
                int r0 = bm + wm + im * 16 + g;      // m = b*2048 + t
                int b  = r0 >> 11, tt = r0 & 2047;
                int n0 = nloc + wn + in * 8 + 2 * t;
                int h  = n0 >> 6, d = n0 & 63;
                if (which < 2) {
                    unsigned* dst = (which == 0) ? g_Q : g_K;
                    size_t base = ((size_t)(b * HH_ + h) * TT_ + tt) * (DD_/2) + (d >> 1);
                    dst[base] = packh2(acc[im][in][0], acc[im][in][1]);
                    dst[base + 8 * (DD_/2)] = packh2(acc[im][in][2], acc[im][in][3]);
                } else {
                    __half* dv = (__half*)g_Vt;
                    size_t bb = ((size_t)(b * HH_ + h) * DD_ + d) * TT_ + tt;
                    dv[bb         ] = __float2half_rn(acc[im][in][0]);
                    dv[bb + TT_   ] = __float2half_rn(acc[im][in][1]);
                    dv[bb + 8     ] = __float2half_rn(acc[im][in][2]);
                    dv[bb + TT_+8 ] = __float2half_rn(acc[im][in][3]);
                }
            }
        }
    }
}

// ============================================================================
// Flash attention (causal), register-resident P.
// CTA = 256 q-rows of one (b,h), 8 warps x 32 q-rows. K/V^T 64-tiles, 2-stage.
// S fragment layout == PV A-fragment layout -> P never touches SMEM.
// ============================================================================
// bytes: sQ[256][72h] @0 (36864), sK[2][64][72h] @36864 (18432),
//        sVt[2][64][72h] @55296 (18432)
#define A_K_OFF 36864u
#define A_V_OFF 55296u
#define A_STG_B 9216u
#define ATTN_SMEM_BYTES 73728

__global__ void __launch_bounds__(256, 1) attn_kernel()
{
    extern __shared__ unsigned smem[];
    const unsigned sbase = smem_u32(smem);

    const int bh = blockIdx.y;                    // b*16 + h
    const int qt = gridDim.x - 1 - blockIdx.x;    // biggest tiles first
    const int q0 = qt * 256;
    const int nkt = (q0 >> 6) + 4;                // k-tiles: kt = 0 .. q0+192

    const __half* Qp  = (const __half*)g_Q  + (size_t)bh * TT_ * DD_;
    const __half* Kp  = (const __half*)g_K  + (size_t)bh * TT_ * DD_;
    const __half* Vtp = (const __half*)g_Vt + (size_t)bh * DD_ * TT_;

    const int tid = threadIdx.x;
    const int warp = tid >> 5, lane = tid & 31;
    const int g = lane >> 2, t = lane & 3;

    // ldmatrix per-lane relative offsets
    unsigned qRel[2], kRel[4], vRel[4];
    {
        int rA = (lane & 15), kA = (lane >> 4) * 8;
        #pragma unroll
        for (int im = 0; im < 2; im++)
            qRel[im] = (unsigned)((warp * 32 + im * 16 + rA) * 72 + kA) * 2u;
        int rB = ((lane >> 4) & 1) * 8 + (lane & 7);
        int kB = ((lane >> 3) & 1) * 8;
        #pragma unroll
        for (int j = 0; j < 4; j++) {
            unsigned rel = (unsigned)((j * 16 + rB) * 72 + kB) * 2u;
            kRel[j] = A_K_OFF + rel;
            vRel[j] = A_V_OFF + rel;
        }
    }

    // ---- prologue: Q (256x64) + K/V stage 0 ----
    {
        #pragma unroll
        for (int i = 0; i < 8; i++) {                     // Q: 2048 chunks
            int id = tid + (i << 8);
            int r = id >> 3, c = id & 7;
            cpa(sbase + (unsigned)r * 144u + (unsigned)c * 16u,
                Qp + (size_t)(q0 + r) * DD_ + c * 8);
        }
        #pragma unroll
        for (int i = 0; i < 2; i++) {                     // K,V: 512 chunks each
            int id = tid + (i << 8);
            int r = id >> 3, c = id & 7;
            cpa(sbase + A_K_OFF + (unsigned)r * 144u + (unsigned)c * 16u,
                Kp + (size_t)r * DD_ + c * 8);
            cpa(sbase + A_V_OFF + (unsigned)r * 144u + (unsigned)c * 16u,
                Vtp + (size_t)r * TT_ + c * 8);
        }
        CP_COMMIT();
    }

    float m[2][2], l[2][2];
    #pragma unroll
    for (int i = 0; i < 2; i++)
        #pragma unroll
        for (int j = 0; j < 2; j++) { m[i][j] = -INFINITY; l[i][j] = 0.f; }

    float o[2][8][4];
    #pragma unroll
    for (int im = 0; im < 2; im++)
        #pragma unroll
        for (int in = 0; in < 8; in++)
            #pragma unroll
            for (int r = 0; r < 4; r++) o[im][in][r] = 0.f;

    const int wrow_min = q0 + warp * 32;

    #pragma unroll 1
    for (int it = 0; it < nkt; ++it) {
        const int kt = it * 64;
        const int s = it & 1;
        if (it + 1 < nkt) {
            const int ns = s ^ 1;
            const int kn = kt + 64;
            #pragma unroll
            for (int i = 0; i < 2; i++) {
                int id = tid + (i << 8);
                int r = id >> 3, c = id & 7;
                cpa(sbase + A_K_OFF + (unsigned)ns * A_STG_B + (unsigned)r * 144u + (unsigned)c * 16u,
                    Kp + (size_t)(kn + r) * DD_ + c * 8);
                cpa(sbase + A_V_OFF + (unsigned)ns * A_STG_B + (unsigned)r * 144u + (unsigned)c * 16u,
                    Vtp + (size_t)r * TT_ + kn + c * 8);
            }
            CP_COMMIT();
            CP_WAIT1();
        } else {
            CP_WAIT0();
        }
        __syncthreads();

        if (kt < wrow_min + 32) {
            const unsigned stgK = sbase + (unsigned)s * A_STG_B;

            // ---- S = Q K^T ----
            float sreg[2][8][4];
            #pragma unroll
            for (int im = 0; im < 2; im++)
                #pragma unroll
                for (int in = 0; in < 8; in++)
                    #pragma unroll
                    for (int r = 0; r < 4; r++) sreg[im][in][r] = 0.f;

            #pragma unroll
            for (int ks8 = 0; ks8 < 4; ks8++) {
                const unsigned ko = (unsigned)ks8 * 32u;
                unsigned qa[2][4], kb[8][2];
                #pragma unroll
                for (int im = 0; im < 2; im++)
                    ldsm4(qa[im], sbase + qRel[im] + ko);
                #pragma unroll
                for (int j = 0; j < 4; j++)
                    ldsm4(&kb[2*j][0], stgK + kRel[j] + ko);
                #pragma unroll
                for (int im = 0; im < 2; im++)
                    #pragma unroll
                    for (int in = 0; in < 8; in++)
                        mma16(sreg[im][in], qa[im], kb[in]);
            }

            // ---- scale, causal mask, row max per (im, half) ----
            const bool needmask = (kt + 63 > wrow_min);
            float mx[2][2];
            #pragma unroll
            for (int im = 0; im < 2; im++) {
                const int rqa = wrow_min + im * 16 + g;
                const int rqb = rqa + 8;
                float a0 = -INFINITY, a1 = -INFINITY;
                #pragma unroll
                for (int in = 0; in < 8; in++) {
                    int c = kt + in * 8 + 2 * t;
                    float x0 = sreg[im][in][0] * SOFTMAX_SCL;
                    float x1 = sreg[im][in][1] * SOFTMAX_SCL;
                    float x2 = sreg[im][in][2] * SOFTMAX_SCL;
                    float x3 = sreg[im][in][3] * SOFTMAX_SCL;
                    if (needmask) {
                        if (c     > rqa) x0 = -INFINITY;
                        if (c + 1 > rqa) x1 = -INFINITY;
                        if (c     > rqb) x2 = -INFINITY;
                        if (c + 1 > rqb) x3 = -INFINITY;
                    }
                    sreg[im][in][0] = x0; sreg[im][in][1] = x1;
                    sreg[im][in][2] = x2; sreg[im][in][3] = x3;
                    a0 = fmaxf(a0, fmaxf(x0, x1));
                    a1 = fmaxf(a1, fmaxf(x2, x3));
                }
                a0 = fmaxf(a0, __shfl_xor_sync(0xffffffffu, a0, 1));
                a0 = fmaxf(a0, __shfl_xor_sync(0xffffffffu, a0, 2));
                a1 = fmaxf(a1, __shfl_xor_sync(0xffffffffu, a1, 1));
                a1 = fmaxf(a1, __shfl_xor_sync(0xffffffffu, a1, 2));
                mx[im][0] = a0; mx[im][1] = a1;
            }

            float cor[2][2];
            #pragma unroll
            for (int im = 0; im < 2; im++)
                #pragma unroll
                for (int hf = 0; hf < 2; hf++) {
                    float nm = fmaxf(m[im][hf], mx[im][hf]);
                    cor[im][hf] = ex2(m[im][hf] - nm);
                    m[im][hf] = nm;
                }

            // ---- P = 2^(x-m) in place, row sums ----
            #pragma unroll
            for (int im = 0; im < 2; im++) {
                float s0 = 0.f, s1 = 0.f;
                #pragma unroll
                for (int in = 0; in < 8; in++) {
                    float p0 = ex2(sreg[im][in][0] - m[im][0]);
                    float p1 = ex2(sreg[im][in][1] - m[im][0]);
                    float p2 = ex2(sreg[im][in][2] - m[im][1]);
                    float p3 = ex2(sreg[im][in][3] - m[im][1]);
                    sreg[im][in][0] = p0; sreg[im][in][1] = p1;
                    sreg[im][in][2] = p2; sreg[im][in][3] = p3;
                    s0 += p0 + p1;
                    s1 += p2 + p3;
                }
                s0 += __shfl_xor_sync(0xffffffffu, s0, 1);
                s0 += __shfl_xor_sync(0xffffffffu, s0, 2);
                s1 += __shfl_xor_sync(0xffffffffu, s1, 1);
                s1 += __shfl_xor_sync(0xffffffffu, s1, 2);
                l[im][0] = l[im][0] * cor[im][0] + s0;
                l[im][1] = l[im][1] * cor[im][1] + s1;
            }

            // rescale O
            #pragma unroll
            for (int im = 0; im < 2; im++)
                #pragma unroll
                for (int in = 0; in < 8; in++) {
                    o[im][in][0] *= cor[im][0]; o[im][in][1] *= cor[im][0];
                    o[im][in][2] *= cor[im][1]; o[im][in][3] *= cor[im][1];
                }

            // ---- O += P V : P packed straight from registers ----
            const unsigned stgV = sbase + (unsigned)s * A_STG_B;
            #pragma unroll
            for (int j2 = 0; j2 < 4; j2++) {              // kv k-steps of 16
                const unsigned ko = (unsigned)j2 * 32u;
                unsigned vb[8][2];
                #pragma unroll
                for (int j = 0; j < 4; j++)
                    ldsm4(&vb[2*j][0], stgV + vRel[j] + ko);
                #pragma unroll
                for (int im = 0; im < 2; im++) {
                    unsigned a[4];
                    a[0] = packh2(sreg[im][2*j2  ][0], sreg[im][2*j2  ][1]);
                    a[1] = packh2(sreg[im][2*j2  ][2], sreg[im][2*j2  ][3]);
                    a[2] = packh2(sreg[im][2*j2+1][0], sreg[im][2*j2+1][1]);
                    a[3] = packh2(sreg[im][2*j2+1][2], sreg[im][2*j2+1][3]);
                    #pragma unroll
                    for (int in = 0; in < 8; in++)
                        mma16(o[im][in], a, vb[in]);
                }
            }
        }
        __syncthreads();
    }

    // ---- normalize, write half2 merged-head output ----
    const int b = bh >> 4, h = bh & 15;
    #pragma unroll
    for (int im = 0; im < 2; im++) {
        float inv0 = 1.f / l[im][0], inv1 = 1.f / l[im][1];
        int r0 = q0 + warp * 32 + im * 16 + g;
        #pragma unroll
        for (int in = 0; in < 8; in++) {
            int cu = h * 32 + in * 4 + t;             // half2 unit col
            size_t base0 = ((size_t)(b * TT_ + r0)     * (CC_/2)) + cu;
            size_t base1 = ((size_t)(b * TT_ + r0 + 8) * (CC_/2)) + cu;
            g_Yc[base0] = packh2(o[im][in][0] * inv0, o[im][in][1] * inv0);
            g_Yc[base1] = packh2(o[im][in][2] * inv1, o[im][in][3] * inv1);
        }
    }
}

// ============================================================================
// launch
// ============================================================================
extern "C" void kernel_launch(void* const* d_in, const int* in_sizes, int n_in,
                              void* d_out, int out_size)
{
    const float* X  = (const float*)d_in[0];
    const float* Wq = (const float*)d_in[1];
    const float* Wk = (const float*)d_in[2];
    const float* Wv = (const float*)d_in[3];
    const float* Wo = (const float*)d_in[4];
    float* out = (float*)d_out;

    cudaFuncSetAttribute(gemm_fp16<1>, cudaFuncAttributeMaxDynamicSharedMemorySize,
                         GEMM_SMEM_BYTES);
    cudaFuncSetAttribute(gemm_fp16<0>, cudaFuncAttributeMaxDynamicSharedMemorySize,
                         GEMM_SMEM_BYTES);
    cudaFuncSetAttribute(attn_kernel, cudaFuncAttributeMaxDynamicSharedMemorySize,
                         ATTN_SMEM_BYTES);

    unsigned *Xt = nullptr, *Wt = nullptr, *Yc = nullptr;
    cudaGetSymbolAddress((void**)&Xt, g_Xt);
    cudaGetSymbolAddress((void**)&Wt, g_Wt);
    cudaGetSymbolAddress((void**)&Yc, g_Yc);

    // 0) fp16 pre-conversion
    conv_kernel<<<8192, 256>>>((const float4*)X, (const float4*)Wq,
                               (const float4*)Wk, (const float4*)Wv,
                               (const float4*)Wo);

    // 1) QKV: M=4096, N=3072 (12 tiles of 256), K=1024
    gemm_fp16<1><<<dim3(12, 32), 256, GEMM_SMEM_BYTES>>>(
        (const __half*)Xt, (const __half*)Wt, nullptr);

    // 2) attention: grid = (q-tiles=8, b*h=32)
    attn_kernel<<<dim3(8, 32), 256, ATTN_SMEM_BYTES>>>();

    // 3) output projection: M=4096, N=1024 (4 tiles of 256), K=1024
    gemm_fp16<0><<<dim3(4, 32), 256, GEMM_SMEM_BYTES>>>(
        (const __half*)Yc, (const __half*)Wt + 3*1024*1024, out);
}

// round 7
// speedup vs baseline: 1.9625x; 1.0293x over previous
#include <cuda_runtime.h>
#include <cuda_fp16.h>
#include <cstdint>
#include <cstdio>

// ---------------- problem constants ----------------
#define BB_ 2
#define TT_ 2048
#define CC_ 1024
#define HH_ 16
#define DD_ 64

// exp(s/8) = 2^(s * log2(e)/8); folded into Q at the QKV epilogue
#define SOFTMAX_SCL 0.18033688011112042f

// ---------------- scratch: fp16 stored as unsigned (half2 units) ----------------
__device__ __align__(16) unsigned g_Xt[BB_*TT_*CC_/2];      // X fp16 [m][k]
__device__ __align__(16) unsigned g_Wt[4*CC_*CC_/2];        // Wq|Wk|Wv|Wo fp16 [n][k]
__device__ __align__(16) unsigned g_Q [BB_*HH_*TT_*DD_/2];  // [b,h,t,d]  (pre-scaled)
__device__ __align__(16) unsigned g_K [BB_*HH_*TT_*DD_/2];  // [b,h,t,d]
__device__ __align__(16) unsigned g_Vt[BB_*HH_*TT_*DD_/2];  // TRANSPOSED [b,h,d,t]
__device__ __align__(16) unsigned g_Yc[BB_*TT_*CC_/2];      // merged heads [b,t,c]

// ---------------- helpers ----------------
__device__ __forceinline__ float ex2(float x) {
    float y;
    asm("ex2.approx.f32 %0, %1;" : "=f"(y) : "f"(x));
    return y;
}
__device__ __forceinline__ unsigned ex2h2(unsigned x) {
    unsigned y;
    asm("ex2.approx.f16x2 %0, %1;" : "=r"(y) : "r"(x));
    return y;
}
__device__ __forceinline__ unsigned hsub2(unsigned a, unsigned b) {
    unsigned y;
    asm("sub.f16x2 %0, %1, %2;" : "=r"(y) : "r"(a), "r"(b));
    return y;
}
__device__ __forceinline__ unsigned packh2(float a, float b) {
    __half2 h = __floats2half2_rn(a, b);
    return *(unsigned*)&h;
}
__device__ __forceinline__ void mma16(float* d, const unsigned* a, const unsigned* b) {
    asm volatile(
        "mma.sync.aligned.m16n8k16.row.col.f32.f16.f16.f32 "
        "{%0,%1,%2,%3},{%4,%5,%6,%7},{%8,%9},{%0,%1,%2,%3};"
        : "+f"(d[0]), "+f"(d[1]), "+f"(d[2]), "+f"(d[3])
        : "r"(a[0]), "r"(a[1]), "r"(a[2]), "r"(a[3]),
          "r"(b[0]), "r"(b[1]));
}
__device__ __forceinline__ void ldsm4(unsigned* r, unsigned addr) {
    asm volatile("ldmatrix.sync.aligned.m8n8.x4.shared.b16 {%0,%1,%2,%3}, [%4];"
        : "=r"(r[0]), "=r"(r[1]), "=r"(r[2]), "=r"(r[3]) : "r"(addr));
}
__device__ __forceinline__ void cpa(unsigned dst, const void* src) {
    asm volatile("cp.async.cg.shared.global [%0], [%1], 16;" :: "r"(dst), "l"(src));
}
#define CP_COMMIT() asm volatile("cp.async.commit_group;")
#define CP_WAIT1()  asm volatile("cp.async.wait_group 1;")
#define CP_WAIT0()  asm volatile("cp.async.wait_group 0;")
__device__ __forceinline__ unsigned smem_u32(const void* p) {
    return (unsigned)__cvta_generic_to_shared(p);
}

// ============================================================================
// one-shot fp16 conversion: X (1M float4) + 4 weights (256K float4 each)
// ============================================================================
__global__ void __launch_bounds__(256) conv_kernel(
    const float4* __restrict__ X,  const float4* __restrict__ Wq,
    const float4* __restrict__ Wk, const float4* __restrict__ Wv,
    const float4* __restrict__ Wo)
{
    int i = blockIdx.x * 256 + threadIdx.x;          // 0 .. 2M-1
    const float4* src;
    uint2* dst;
    if (i < (1 << 20)) {
        src = X + i;
        dst = (uint2*)g_Xt + i;
    } else {
        int j = i - (1 << 20);
        int w = j >> 18, r = j & 0x3FFFF;
        const float4* s4 = (w == 0) ? Wq : (w == 1) ? Wk : (w == 2) ? Wv : Wo;
        src = s4 + r;
        dst = (uint2*)g_Wt + (w << 18) + r;
    }
    float4 v = *src;
    *dst = make_uint2(packh2(v.x, v.y), packh2(v.z, v.w));
}

// ============================================================================
// fp16 GEMM: C[m,n] = sum_k A[m,k]*B[n,k]  (NT), K=1024.
// CTA 128x128, 4 warps (2m x 2n), warp tile 64x64, m16n8k16 + ldmatrix.x4.
// 128 threads + 73.7KB smem -> 2 CTAs/SM (barrier overlap across CTAs).
// k-chunk 64 halves, 2-stage cp.async.
// MODE 1: epilogue -> g_Q (pre-scaled) / g_K ([b,h,t,d]) or g_Vt ([b,h,d,t]).
// MODE 0: A=g_Yc, writes fp32 Cout.
// ============================================================================
#define G_ROW_B 144u
#define G_A_B   18432u          // A block bytes (128*144)
#define G_STG_B 36864u          // A+B per stage
#define GEMM_SMEM_BYTES (2*36864)

template<int MODE>
__global__ void __launch_bounds__(128) gemm_fp16(
    const __half* __restrict__ A,
    const __half* __restrict__ B,
    float* __restrict__ Cout)
{
    extern __shared__ unsigned smem[];
    const unsigned sbase = smem_u32(smem);

    const int tid  = threadIdx.x;
    const int bm   = blockIdx.y * 128;
    const int bn   = blockIdx.x * 128;
    const int warp = tid >> 5, lane = tid & 31;
    const int g = lane >> 2, t = lane & 3;
    const int wm = (warp & 1) * 64;          // warp m offset
    const int wn = (warp >> 1) * 64;         // warp n offset

    const __half* Ap = A + (size_t)bm * 1024;
    const __half* Bp = B + (size_t)bn * 1024;

    float acc[4][8][4];
    #pragma unroll
    for (int i = 0; i < 4; i++)
        #pragma unroll
        for (int j = 0; j < 8; j++)
            #pragma unroll
            for (int r = 0; r < 4; r++) acc[i][j][r] = 0.f;

    // ldmatrix per-lane relative byte offsets
    unsigned aRel[4], bRel[4];
    {
        int rA = (lane & 15), kA = (lane >> 4) * 8;
        #pragma unroll
        for (int im = 0; im < 4; im++)
            aRel[im] = (unsigned)((wm + im * 16 + rA) * 72 + kA) * 2u;
        int rB = ((lane >> 4) & 1) * 8 + (lane & 7);
        int kB = ((lane >> 3) & 1) * 8;
        #pragma unroll
        for (int j = 0; j < 4; j++)
            bRel[j] = G_A_B + (unsigned)((wn + j * 16 + rB) * 72 + kB) * 2u;
    }

    auto load_stage = [&](int s, int k0) {
        const unsigned st = sbase + (unsigned)s * G_STG_B;
        #pragma unroll
        for (int i = 0; i < 8; i++) {                       // A: 1024 chunks
            int id = tid + (i << 7);
            int r = id >> 3, c = id & 7;
            cpa(st + (unsigned)r * G_ROW_B + (unsigned)c * 16u,
                Ap + (size_t)r * 1024 + k0 + c * 8);
        }
        #pragma unroll
        for (int i = 0; i < 8; i++) {                       // B: 1024 chunks
            int id = tid + (i << 7);
            int r = id >> 3, c = id & 7;
            cpa(st + G_A_B + (unsigned)r * G_ROW_B + (unsigned)c * 16u,
                Bp + (size_t)r * 1024 + k0 + c * 8);
        }
    };

    load_stage(0, 0);
    CP_COMMIT();

    #pragma unroll 1
    for (int i = 0; i < 16; ++i) {
        const int s = i & 1;
        if (i + 1 < 16) {
            load_stage(s ^ 1, (i + 1) * 64);
            CP_COMMIT();
            CP_WAIT1();
        } else {
            CP_WAIT0();
        }
        __syncthreads();

        const unsigned stg = sbase + (unsigned)s * G_STG_B;
        #pragma unroll
        for (int ks8 = 0; ks8 < 4; ks8++) {                 // 4 k-steps of 16
            const unsigned ko = (unsigned)ks8 * 32u;        // 16 halves = 32B
            unsigned afr[4][4], bfr[8][2];
            #pragma unroll
            for (int im = 0; im < 4; im++)
                ldsm4(afr[im], stg + aRel[im] + ko);
            #pragma unroll
            for (int j = 0; j < 4; j++)
                ldsm4(&bfr[2*j][0], stg + bRel[j] + ko);
            #pragma unroll
            for (int im = 0; im < 4; im++)
                #pragma unroll
                for (int in = 0; in < 8; in++)
                    mma16(acc[im][in], afr[im], bfr[in]);
        }
        __syncthreads();
    }

    // ---------------- epilogue ----------------
    if (MODE == 0) {
        #pragma unroll
        for (int im = 0; im < 4; im++) {
            #pragma unroll
            for (int in = 0; in < 8; in++) {
                int r0 = bm + wm + im * 16 + g;
                int c0 = bn + wn + in * 8 + 2 * t;
                *(float2*)(Cout + (size_t)r0 * 1024 + c0) =
                    make_float2(acc[im][in][0], acc[im][in][1]);
                *(float2*)(Cout + (size_t)(r0 + 8) * 1024 + c0) =
                    make_float2(acc[im][in][2], acc[im][in][3]);
            }
        }
    } else {
        const int which = bn >> 10;
        const int nloc  = bn & 1023;
        const float qs = (which == 0) ? SOFTMAX_SCL : 1.f;  // fold softmax scale into Q
        #pragma unroll
        for (int im = 0; im < 4; im++) {
            #pragma unroll
            for (int in = 0; in < 8; in++) {
                int r0 = bm + wm + im * 16 + g;      // m = b*2048 + t
                int b  = r0 >> 11, tt = r0 & 2047;
                int n0 = nloc + wn + in * 8 + 2 * t;
                int h  = n0 >> 6, d = n0 & 63;
                if (which < 2) {
                    unsigned* dst = (which == 0) ? g_Q : g_K;
                    size_t base = ((size_t)(b * HH_ + h) * TT_ + tt) * (DD_/2) + (d >> 1);
                    dst[base] = packh2(acc[im][in][0] * qs, acc[im][in][1] * qs);
                    dst[base + 8 * (DD_/2)] = packh2(acc[im][in][2] * qs, acc[im][in][3] * qs);
                } else {
                    __half* dv = (__half*)g_Vt;
                    size_t bb = ((size_t)(b * HH_ + h) * DD_ + d) * TT_ + tt;
                    dv[bb         ] = __float2half_rn(acc[im][in][0]);
                    dv[bb + TT_   ] = __float2half_rn(acc[im][in][1]);
                    dv[bb + 8     ] = __float2half_rn(acc[im][in][2]);
                    dv[bb + TT_+8 ] = __float2half_rn(acc[im][in][3]);
                }
            }
        }
    }
}

// ============================================================================
// Flash attention (causal), register-resident P, f16x2 softmax,
// row sums via ones-column mma (l = o[im][8]).
// CTA = 128 q-rows of one (b,h), 4 warps x 32 q-rows, 128 threads,
// 55.3KB smem -> 2 CTAs/SM. K/V^T 64-tiles, 2-stage cp.async.
// ============================================================================
// bytes: sQ[128][72h] @0 (18432), sK[2][64][72h] @18432 (18432),
//        sVt[2][64][72h] @36864 (18432)
#define A_K_OFF 18432u
#define A_V_OFF 36864u
#define A_STG_B 9216u
#define ATTN_SMEM_BYTES 55296

__global__ void __launch_bounds__(128) attn_kernel()
{
    extern __shared__ unsigned smem[];
    const unsigned sbase = smem_u32(smem);

    const int bh = blockIdx.y;                    // b*16 + h
    const int qt = gridDim.x - 1 - blockIdx.x;    // biggest tiles first
    const int q0 = qt * 128;
    const int nkt = (q0 >> 6) + 2;                // k-tiles: kt = 0 .. q0+64

    const __half* Qp  = (const __half*)g_Q  + (size_t)bh * TT_ * DD_;
    const __half* Kp  = (const __half*)g_K  + (size_t)bh * TT_ * DD_;
    const __half* Vtp = (const __half*)g_Vt + (size_t)bh * DD_ * TT_;

    const int tid = threadIdx.x;
    const int warp = tid >> 5, lane = tid & 31;
    const int g = lane >> 2, t = lane & 3;

    // ldmatrix per-lane relative offsets
    unsigned qRel[2], kRel[4], vRel[4];
    {
        int rA = (lane & 15), kA = (lane >> 4) * 8;
        #pragma unroll
        for (int im = 0; im < 2; im++)
            qRel[im] = (unsigned)((warp * 32 + im * 16 + rA) * 72 + kA) * 2u;
        int rB = ((lane >> 4) & 1) * 8 + (lane & 7);
        int kB = ((lane >> 3) & 1) * 8;
        #pragma unroll
        for (int j = 0; j < 4; j++) {
            unsigned rel = (unsigned)((j * 16 + rB) * 72 + kB) * 2u;
            kRel[j] = A_K_OFF + rel;
            vRel[j] = A_V_OFF + rel;
        }
    }

    // ---- prologue: Q (128x64) + K/V stage 0 ----
    {
        #pragma unroll
        for (int i = 0; i < 8; i++) {                     // Q: 1024 chunks
            int id = tid + (i << 7);
            int r = id >> 3, c = id & 7;
            cpa(sbase + (unsigned)r * 144u + (unsigned)c * 16u,
                Qp + (size_t)(q0 + r) * DD_ + c * 8);
        }
        #pragma unroll
        for (int i = 0; i < 4; i++) {                     // K,V: 512 chunks each
            int id = tid + (i << 7);
            int r = id >> 3, c = id & 7;
            cpa(sbase + A_K_OFF + (unsigned)r * 144u + (unsigned)c * 16u,
                Kp + (size_t)r * DD_ + c * 8);
            cpa(sbase + A_V_OFF + (unsigned)r * 144u + (unsigned)c * 16u,
                Vtp + (size_t)r * TT_ + c * 8);
        }
        CP_COMMIT();
    }

    float m[2][2];
    #pragma unroll
    for (int i = 0; i < 2; i++)
        #pragma unroll
        for (int j = 0; j < 2; j++) m[i][j] = -INFINITY;

    // o[im][0..7] = output, o[im][8] = row sums (V ones column)
    float o[2][9][4];
    #pragma unroll
    for (int im = 0; im < 2; im++)
        #pragma unroll
        for (int in = 0; in < 9; in++)
            #pragma unroll
            for (int r = 0; r < 4; r++) o[im][in][r] = 0.f;

    const unsigned ones_b[2] = {0x3C003C00u, 0x3C003C00u};  // half2(1,1)
    const int wrow_min = q0 + warp * 32;

    #pragma unroll 1
    for (int it = 0; it < nkt; ++it) {
        const int kt = it * 64;
        const int s = it & 1;
        if (it + 1 < nkt) {
            const int ns = s ^ 1;
            const int kn = kt + 64;
            #pragma unroll
            for (int i = 0; i < 4; i++) {
                int id = tid + (i << 7);
                int r = id >> 3, c = id & 7;
                cpa(sbase + A_K_OFF + (unsigned)ns * A_STG_B + (unsigned)r * 144u + (unsigned)c * 16u,
                    Kp + (size_t)(kn + r) * DD_ + c * 8);
                cpa(sbase + A_V_OFF + (unsigned)ns * A_STG_B + (unsigned)r * 144u + (unsigned)c * 16u,
                    Vtp + (size_t)r * TT_ + kn + c * 8);
            }
            CP_COMMIT();
            CP_WAIT1();
        } else {
            CP_WAIT0();
        }
        __syncthreads();

        if (kt < wrow_min + 32) {
            const unsigned stgK = sbase + (unsigned)s * A_STG_B;

            // ---- S = Q K^T (pre-scaled, log2 domain) ----
            float sreg[2][8][4];
            #pragma unroll
            for (int im = 0; im < 2; im++)
                #pragma unroll
                for (int in = 0; in < 8; in++)
                    #pragma unroll
                    for (int r = 0; r < 4; r++) sreg[im][in][r] = 0.f;

            #pragma unroll
            for (int ks8 = 0; ks8 < 4; ks8++) {
                const unsigned ko = (unsigned)ks8 * 32u;
                unsigned qa[2][4], kb[8][2];
                #pragma unroll
                for (int im = 0; im < 2; im++)
                    ldsm4(qa[im], sbase + qRel[im] + ko);
                #pragma unroll
                for (int j = 0; j < 4; j++)
                    ldsm4(&kb[2*j][0], stgK + kRel[j] + ko);
                #pragma unroll
                for (int im = 0; im < 2; im++)
                    #pragma unroll
                    for (int in = 0; in < 8; in++)
                        mma16(sreg[im][in], qa[im], kb[in]);
            }

            // ---- causal mask + row max (fp32) ----
            const bool needmask = (kt + 63 > wrow_min);
            float mx[2][2];
            #pragma unroll
            for (int im = 0; im < 2; im++) {
                const int rqa = wrow_min + im * 16 + g;
                const int rqb = rqa + 8;
                float a0 = -INFINITY, a1 = -INFINITY;
                #pragma unroll
                for (int in = 0; in < 8; in++) {
                    int c = kt + in * 8 + 2 * t;
                    float x0 = sreg[im][in][0];
                    float x1 = sreg[im][in][1];
                    float x2 = sreg[im][in][2];
                    float x3 = sreg[im][in][3];
                    if (needmask) {
                        if (c     > rqa) x0 = -INFINITY;
                        if (c + 1 > rqa) x1 = -INFINITY;
                        if (c     > rqb) x2 = -INFINITY;
                        if (c + 1 > rqb) x3 = -INFINITY;
                    }
                    sreg[im][in][0] = x0; sreg[im][in][1] = x1;
                    sreg[im][in][2] = x2; sreg[im][in][3] = x3;
                    a0 = fmaxf(a0, fmaxf(x0, x1));
                    a1 = fmaxf(a1, fmaxf(x2, x3));
                }
                a0 = fmaxf(a0, __shfl_xor_sync(0xffffffffu, a0, 1));
                a0 = fmaxf(a0, __shfl_xor_sync(0xffffffffu, a0, 2));
                a1 = fmaxf(a1, __shfl_xor_sync(0xffffffffu, a1, 1));
                a1 = fmaxf(a1, __shfl_xor_sync(0xffffffffu, a1, 2));
                mx[im][0] = a0; mx[im][1] = a1;
            }

            float cor[2][2];
            #pragma unroll
            for (int im = 0; im < 2; im++)
                #pragma unroll
                for (int hf = 0; hf < 2; hf++) {
                    float nm = fmaxf(m[im][hf], mx[im][hf]);
                    cor[im][hf] = ex2(m[im][hf] - nm);
                    m[im][hf] = nm;
                }

            // ---- P = 2^(x-m) via f16x2 MUFU; pk is PV-A-fragment-ready ----
            unsigned pk[2][8][2];
            #pragma unroll
            for (int im = 0; im < 2; im++) {
                const unsigned mh0 = packh2(m[im][0], m[im][0]);
                const unsigned mh1 = packh2(m[im][1], m[im][1]);
                #pragma unroll
                for (int in = 0; in < 8; in++) {
                    unsigned xa = packh2(sreg[im][in][0], sreg[im][in][1]);
                    unsigned xb = packh2(sreg[im][in][2], sreg[im][in][3]);
                    pk[im][in][0] = ex2h2(hsub2(xa, mh0));
                    pk[im][in][1] = ex2h2(hsub2(xb, mh1));
                }
            }

            // rescale O (incl. sum column 8)
            #pragma unroll
            for (int im = 0; im < 2; im++)
                #pragma unroll
                for (int in = 0; in < 9; in++) {
                    o[im][in][0] *= cor[im][0]; o[im][in][1] *= cor[im][0];
                    o[im][in][2] *= cor[im][1]; o[im][in][3] *= cor[im][1];
                }

            // ---- O += P V  (+ row sums via ones column) ----
            const unsigned stgV = sbase + (unsigned)s * A_STG_B;
            #pragma unroll
            for (int j2 = 0; j2 < 4; j2++) {              // kv k-steps of 16
                const unsigned ko = (unsigned)j2 * 32u;
                unsigned vb[8][2];
                #pragma unroll
                for (int j = 0; j < 4; j++)
                    ldsm4(&vb[2*j][0], stgV + vRel[j] + ko);
                #pragma unroll
                for (int im = 0; im < 2; im++) {
                    unsigned a[4];
                    a[0] = pk[im][2*j2  ][0];
                    a[1] = pk[im][2*j2  ][1];
                    a[2] = pk[im][2*j2+1][0];
                    a[3] = pk[im][2*j2+1][1];
                    #pragma unroll
                    for (int in = 0; in < 8; in++)
                        mma16(o[im][in], a, vb[in]);
                    mma16(o[im][8], a, ones_b);           // row sums
                }
            }
        }
        __syncthreads();
    }

    // ---- normalize by l = o[im][8], write half2 merged-head output ----
    const int b = bh >> 4, h = bh & 15;
    #pragma unroll
    for (int im = 0; im < 2; im++) {
        float inv0 = 1.f / o[im][8][0];
        float inv1 = 1.f / o[im][8][2];
        int r0 = q0 + warp * 32 + im * 16 + g;
        #pragma unroll
        for (int in = 0; in < 8; in++) {
            int cu = h * 32 + in * 4 + t;             // half2 unit col
            size_t base0 = ((size_t)(b * TT_ + r0)     * (CC_/2)) + cu;
            size_t base1 = ((size_t)(b * TT_ + r0 + 8) * (CC_/2)) + cu;
            g_Yc[base0] = packh2(o[im][in][0] * inv0, o[im][in][1] * inv0);
            g_Yc[base1] = packh2(o[im][in][2] * inv1, o[im][in][3] * inv1);
        }
    }
}

// ============================================================================
// launch
// ============================================================================
extern "C" void kernel_launch(void* const* d_in, const int* in_sizes, int n_in,
                              void* d_out, int out_size)
{
    const float* X  = (const float*)d_in[0];
    const float* Wq = (const float*)d_in[1];
    const float* Wk = (const float*)d_in[2];
    const float* Wv = (const float*)d_in[3];
    const float* Wo = (const float*)d_in[4];
    float* out = (float*)d_out;

    cudaFuncSetAttribute(gemm_fp16<1>, cudaFuncAttributeMaxDynamicSharedMemorySize,
                         GEMM_SMEM_BYTES);
    cudaFuncSetAttribute(gemm_fp16<0>, cudaFuncAttributeMaxDynamicSharedMemorySize,
                         GEMM_SMEM_BYTES);
    cudaFuncSetAttribute(attn_kernel, cudaFuncAttributeMaxDynamicSharedMemorySize,
                         ATTN_SMEM_BYTES);

    unsigned *Xt = nullptr, *Wt = nullptr, *Yc = nullptr;
    cudaGetSymbolAddress((void**)&Xt, g_Xt);
    cudaGetSymbolAddress((void**)&Wt, g_Wt);
    cudaGetSymbolAddress((void**)&Yc, g_Yc);

    // 0) fp16 pre-conversion
    conv_kernel<<<8192, 256>>>((const float4*)X, (const float4*)Wq,
                               (const float4*)Wk, (const float4*)Wv,
                               (const float4*)Wo);

    // 1) QKV: M=4096, N=3072 (24 tiles of 128), K=1024
    gemm_fp16<1><<<dim3(24, 32), 128, GEMM_SMEM_BYTES>>>(
        (const __half*)Xt, (const __half*)Wt, nullptr);

    // 2) attention: grid = (q-tiles=16, b*h=32)
    attn_kernel<<<dim3(16, 32), 128, ATTN_SMEM_BYTES>>>();

    // 3) output projection: M=4096, N=1024 (8 tiles of 128), K=1024
    gemm_fp16<0><<<dim3(8, 32), 128, GEMM_SMEM_BYTES>>>(
        (const __half*)Yc, (const __half*)Wt + 3*1024*1024, out);
}

// round 8
// speedup vs baseline: 2.1955x; 1.1187x over previous
#include <cuda_runtime.h>
#include <cuda_fp16.h>
#include <cstdint>
#include <cstdio>

// ---------------- problem constants ----------------
#define BB_ 2
#define TT_ 2048
#define CC_ 1024
#define HH_ 16
#define DD_ 64

// exp(s/8) = 2^(s * log2(e)/8); folded into Q at the QKV epilogue
#define SOFTMAX_SCL 0.18033688011112042f

// ---------------- scratch: fp16 stored as unsigned (half2 units) ----------------
__device__ __align__(16) unsigned g_Xt[BB_*TT_*CC_/2];      // X fp16 [m][k]
__device__ __align__(16) unsigned g_Wt[4*CC_*CC_/2];        // Wq|Wk|Wv|Wo fp16 [n][k]
__device__ __align__(16) unsigned g_Q [BB_*HH_*TT_*DD_/2];  // [b,h,t,d]  (pre-scaled)
__device__ __align__(16) unsigned g_K [BB_*HH_*TT_*DD_/2];  // [b,h,t,d]
__device__ __align__(16) unsigned g_V [BB_*HH_*TT_*DD_/2];  // [b,h,t,d]
__device__ __align__(16) unsigned g_Yc[BB_*TT_*CC_/2];      // merged heads [b,t,c]

// ---------------- helpers ----------------
__device__ __forceinline__ float ex2(float x) {
    float y;
    asm("ex2.approx.f32 %0, %1;" : "=f"(y) : "f"(x));
    return y;
}
__device__ __forceinline__ unsigned ex2h2(unsigned x) {
    unsigned y;
    asm("ex2.approx.f16x2 %0, %1;" : "=r"(y) : "r"(x));
    return y;
}
__device__ __forceinline__ unsigned hsub2(unsigned a, unsigned b) {
    unsigned y;
    asm("sub.f16x2 %0, %1, %2;" : "=r"(y) : "r"(a), "r"(b));
    return y;
}
__device__ __forceinline__ unsigned packh2(float a, float b) {
    __half2 h = __floats2half2_rn(a, b);
    return *(unsigned*)&h;
}
__device__ __forceinline__ void mma16(float* d, const unsigned* a, const unsigned* b) {
    asm volatile(
        "mma.sync.aligned.m16n8k16.row.col.f32.f16.f16.f32 "
        "{%0,%1,%2,%3},{%4,%5,%6,%7},{%8,%9},{%0,%1,%2,%3};"
        : "+f"(d[0]), "+f"(d[1]), "+f"(d[2]), "+f"(d[3])
        : "r"(a[0]), "r"(a[1]), "r"(a[2]), "r"(a[3]),
          "r"(b[0]), "r"(b[1]));
}
__device__ __forceinline__ void ldsm4(unsigned* r, unsigned addr) {
    asm volatile("ldmatrix.sync.aligned.m8n8.x4.shared.b16 {%0,%1,%2,%3}, [%4];"
        : "=r"(r[0]), "=r"(r[1]), "=r"(r[2]), "=r"(r[3]) : "r"(addr));
}
__device__ __forceinline__ void ldsm4t(unsigned* r, unsigned addr) {
    asm volatile("ldmatrix.sync.aligned.m8n8.x4.trans.shared.b16 {%0,%1,%2,%3}, [%4];"
        : "=r"(r[0]), "=r"(r[1]), "=r"(r[2]), "=r"(r[3]) : "r"(addr));
}
__device__ __forceinline__ void cpa(unsigned dst, const void* src) {
    asm volatile("cp.async.cg.shared.global [%0], [%1], 16;" :: "r"(dst), "l"(src));
}
#define CP_COMMIT() asm volatile("cp.async.commit_group;")
#define CP_WAIT0()  asm volatile("cp.async.wait_group 0;")
__device__ __forceinline__ unsigned smem_u32(const void* p) {
    return (unsigned)__cvta_generic_to_shared(p);
}

// ============================================================================
// one-shot fp16 conversion: X (1M float4) + 4 weights (256K float4 each)
// ============================================================================
__global__ void __launch_bounds__(256) conv_kernel(
    const float4* __restrict__ X,  const float4* __restrict__ Wq,
    const float4* __restrict__ Wk, const float4* __restrict__ Wv,
    const float4* __restrict__ Wo)
{
    int i = blockIdx.x * 256 + threadIdx.x;          // 0 .. 2M-1
    const float4* src;
    uint2* dst;
    if (i < (1 << 20)) {
        src = X + i;
        dst = (uint2*)g_Xt + i;
    } else {
        int j = i - (1 << 20);
        int w = j >> 18, r = j & 0x3FFFF;
        const float4* s4 = (w == 0) ? Wq : (w == 1) ? Wk : (w == 2) ? Wv : Wo;
        src = s4 + r;
        dst = (uint2*)g_Wt + (w << 18) + r;
    }
    float4 v = *src;
    *dst = make_uint2(packh2(v.x, v.y), packh2(v.z, v.w));
}

// ============================================================================
// fp16 GEMM: C[m,n] = sum_k A[m,k]*B[n,k]  (NT), K=1024.
// CTA 128x128, 4 warps (2m x 2n), warp tile 64x64, m16n8k16 + ldmatrix.x4.
// 2-stage cp.async with SINGLE __syncthreads per k-chunk
// (wait -> sync -> issue next loads -> compute; barrier proves prev compute done).
// 128 thr + 73.7KB smem -> 2 CTAs/SM.
// MODE 1: epilogue -> g_Q (pre-scaled) / g_K / g_V (all [b,h,t,d], coalesced).
// MODE 0: A=g_Yc, writes fp32 Cout.
// ============================================================================
#define G_ROW_B 144u
#define G_A_B   18432u          // A block bytes (128*144)
#define G_STG_B 36864u          // A+B per stage
#define GEMM_SMEM_BYTES (2*36864)

template<int MODE>
__global__ void __launch_bounds__(128, 2) gemm_fp16(
    const __half* __restrict__ A,
    const __half* __restrict__ B,
    float* __restrict__ Cout)
{
    extern __shared__ unsigned smem[];
    const unsigned sbase = smem_u32(smem);

    const int tid  = threadIdx.x;
    const int bm   = blockIdx.y * 128;
    const int bn   = blockIdx.x * 128;
    const int warp = tid >> 5, lane = tid & 31;
    const int g = lane >> 2, t = lane & 3;
    const int wm = (warp & 1) * 64;          // warp m offset
    const int wn = (warp >> 1) * 64;         // warp n offset

    const __half* Ap = A + (size_t)bm * 1024;
    const __half* Bp = B + (size_t)bn * 1024;

    float acc[4][8][4];
    #pragma unroll
    for (int i = 0; i < 4; i++)
        #pragma unroll
        for (int j = 0; j < 8; j++)
            #pragma unroll
            for (int r = 0; r < 4; r++) acc[i][j][r] = 0.f;

    // ldmatrix per-lane relative byte offsets
    unsigned aRel[4], bRel[4];
    {
        int rA = (lane & 15), kA = (lane >> 4) * 8;
        #pragma unroll
        for (int im = 0; im < 4; im++)
            aRel[im] = (unsigned)((wm + im * 16 + rA) * 72 + kA) * 2u;
        int rB = ((lane >> 4) & 1) * 8 + (lane & 7);
        int kB = ((lane >> 3) & 1) * 8;
        #pragma unroll
        for (int j = 0; j < 4; j++)
            bRel[j] = G_A_B + (unsigned)((wn + j * 16 + rB) * 72 + kB) * 2u;
    }

    auto load_stage = [&](int s, int k0) {
        const unsigned st = sbase + (unsigned)s * G_STG_B;
        #pragma unroll
        for (int i = 0; i < 8; i++) {                       // A: 1024 chunks
            int id = tid + (i << 7);
            int r = id >> 3, c = id & 7;
            cpa(st + (unsigned)r * G_ROW_B + (unsigned)c * 16u,
                Ap + (size_t)r * 1024 + k0 + c * 8);
        }
        #pragma unroll
        for (int i = 0; i < 8; i++) {                       // B: 1024 chunks
            int id = tid + (i << 7);
            int r = id >> 3, c = id & 7;
            cpa(st + G_A_B + (unsigned)r * G_ROW_B + (unsigned)c * 16u,
                Bp + (size_t)r * 1024 + k0 + c * 8);
        }
    };

    load_stage(0, 0);
    CP_COMMIT();

    #pragma unroll 1
    for (int i = 0; i < 16; ++i) {
        const int s = i & 1;
        CP_WAIT0();                 // stage i complete (self)
        __syncthreads();            // visible to all + prev compute done
        if (i + 1 < 16) {
            load_stage(s ^ 1, (i + 1) * 64);
            CP_COMMIT();
        }

        const unsigned stg = sbase + (unsigned)s * G_STG_B;
        #pragma unroll
        for (int ks8 = 0; ks8 < 4; ks8++) {                 // 4 k-steps of 16
            const unsigned ko = (unsigned)ks8 * 32u;        // 16 halves = 32B
            unsigned afr[4][4], bfr[8][2];
            #pragma unroll
            for (int im = 0; im < 4; im++)
                ldsm4(afr[im], stg + aRel[im] + ko);
            #pragma unroll
            for (int j = 0; j < 4; j++)
                ldsm4(&bfr[2*j][0], stg + bRel[j] + ko);
            #pragma unroll
            for (int im = 0; im < 4; im++)
                #pragma unroll
                for (int in = 0; in < 8; in++)
                    mma16(acc[im][in], afr[im], bfr[in]);
        }
    }

    // ---------------- epilogue ----------------
    if (MODE == 0) {
        #pragma unroll
        for (int im = 0; im < 4; im++) {
            #pragma unroll
            for (int in = 0; in < 8; in++) {
                int r0 = bm + wm + im * 16 + g;
                int c0 = bn + wn + in * 8 + 2 * t;
                *(float2*)(Cout + (size_t)r0 * 1024 + c0) =
                    make_float2(acc[im][in][0], acc[im][in][1]);
                *(float2*)(Cout + (size_t)(r0 + 8) * 1024 + c0) =
                    make_float2(acc[im][in][2], acc[im][in][3]);
            }
        }
    } else {
        const int which = bn >> 10;
        const int nloc  = bn & 1023;
        const float qs = (which == 0) ? SOFTMAX_SCL : 1.f;  // fold softmax scale into Q
        unsigned* dst = (which == 0) ? g_Q : (which == 1) ? g_K : g_V;
        #pragma unroll
        for (int im = 0; im < 4; im++) {
            #pragma unroll
            for (int in = 0; in < 8; in++) {
                int r0 = bm + wm + im * 16 + g;      // m = b*2048 + t
                int b  = r0 >> 11, tt = r0 & 2047;
                int n0 = nloc + wn + in * 8 + 2 * t;
                int h  = n0 >> 6, d = n0 & 63;
                size_t base = ((size_t)(b * HH_ + h) * TT_ + tt) * (DD_/2) + (d >> 1);
                dst[base] = packh2(acc[im][in][0] * qs, acc[im][in][1] * qs);
                dst[base + 8 * (DD_/2)] = packh2(acc[im][in][2] * qs, acc[im][in][3] * qs);
            }
        }
    }
}

// ============================================================================
// Flash attention (causal), register-resident P, f16x2 softmax,
// row sums via ones-column mma. V stored [b,h,t,d]; PV B-fragments via
// ldmatrix.x4.trans on kv-rows (no V transpose anywhere).
// CTA = 128 q-rows of one (b,h), 4 warps x 32 q-rows, 128 thr,
// 55.3KB smem -> 2 CTAs/SM. K/V 64-row tiles, 2-stage, single sync per tile.
// ============================================================================
// bytes: sQ[128][72h] @0 (18432), sK[2][64][72h] @18432, sV[2][64][72h] @36864
#define A_K_OFF 18432u
#define A_V_OFF 36864u
#define A_STG_B 9216u
#define ATTN_SMEM_BYTES 55296

__global__ void __launch_bounds__(128, 2) attn_kernel()
{
    extern __shared__ unsigned smem[];
    const unsigned sbase = smem_u32(smem);

    const int bh = blockIdx.y;                    // b*16 + h
    const int qt = gridDim.x - 1 - blockIdx.x;    // biggest tiles first
    const int q0 = qt * 128;
    const int nkt = (q0 >> 6) + 2;                // k-tiles: kt = 0 .. q0+64

    const __half* Qp = (const __half*)g_Q + (size_t)bh * TT_ * DD_;
    const __half* Kp = (const __half*)g_K + (size_t)bh * TT_ * DD_;
    const __half* Vp = (const __half*)g_V + (size_t)bh * TT_ * DD_;

    const int tid = threadIdx.x;
    const int warp = tid >> 5, lane = tid & 31;
    const int g = lane >> 2, t = lane & 3;

    // ldmatrix per-lane relative offsets
    unsigned qRel[2], kRel[4], vRel[4];
    {
        int rA = (lane & 15), kA = (lane >> 4) * 8;
        #pragma unroll
        for (int im = 0; im < 2; im++)
            qRel[im] = (unsigned)((warp * 32 + im * 16 + rA) * 72 + kA) * 2u;
        int rB = ((lane >> 4) & 1) * 8 + (lane & 7);
        int kB = ((lane >> 3) & 1) * 8;
        #pragma unroll
        for (int j = 0; j < 4; j++)
            kRel[j] = A_K_OFF + (unsigned)((j * 16 + rB) * 72 + kB) * 2u;
        // V (trans): lane -> kv row (lane&15), d col = j*16 + (lane>>4)*8
        int rV = lane & 15, cV = (lane >> 4) * 8;
        #pragma unroll
        for (int j = 0; j < 4; j++)
            vRel[j] = A_V_OFF + (unsigned)(rV * 72 + j * 16 + cV) * 2u;
    }

    // ---- prologue: Q (128x64) + K/V stage 0 ----
    {
        #pragma unroll
        for (int i = 0; i < 8; i++) {                     // Q: 1024 chunks
            int id = tid + (i << 7);
            int r = id >> 3, c = id & 7;
            cpa(sbase + (unsigned)r * 144u + (unsigned)c * 16u,
                Qp + (size_t)(q0 + r) * DD_ + c * 8);
        }
        #pragma unroll
        for (int i = 0; i < 4; i++) {                     // K,V: 512 chunks each
            int id = tid + (i << 7);
            int r = id >> 3, c = id & 7;
            cpa(sbase + A_K_OFF + (unsigned)r * 144u + (unsigned)c * 16u,
                Kp + (size_t)r * DD_ + c * 8);
            cpa(sbase + A_V_OFF + (unsigned)r * 144u + (unsigned)c * 16u,
                Vp + (size_t)r * DD_ + c * 8);
        }
        CP_COMMIT();
    }

    float m[2][2];
    #pragma unroll
    for (int i = 0; i < 2; i++)
        #pragma unroll
        for (int j = 0; j < 2; j++) m[i][j] = -INFINITY;

    // o[im][0..7] = output, o[im][8] = row sums (V ones column)
    float o[2][9][4];
    #pragma unroll
    for (int im = 0; im < 2; im++)
        #pragma unroll
        for (int in = 0; in < 9; in++)
            #pragma unroll
            for (int r = 0; r < 4; r++) o[im][in][r] = 0.f;

    const unsigned ones_b[2] = {0x3C003C00u, 0x3C003C00u};  // half2(1,1)
    const int wrow_min = q0 + warp * 32;

    #pragma unroll 1
    for (int it = 0; it < nkt; ++it) {
        const int kt = it * 64;
        const int s = it & 1;
        CP_WAIT0();
        __syncthreads();
        if (it + 1 < nkt) {
            const int ns = s ^ 1;
            const int kn = kt + 64;
            #pragma unroll
            for (int i = 0; i < 4; i++) {
                int id = tid + (i << 7);
                int r = id >> 3, c = id & 7;
                cpa(sbase + A_K_OFF + (unsigned)ns * A_STG_B + (unsigned)r * 144u + (unsigned)c * 16u,
                    Kp + (size_t)(kn + r) * DD_ + c * 8);
                cpa(sbase + A_V_OFF + (unsigned)ns * A_STG_B + (unsigned)r * 144u + (unsigned)c * 16u,
                    Vp + (size_t)(kn + r) * DD_ + c * 8);
            }
            CP_COMMIT();
        }

        if (kt < wrow_min + 32) {
            const unsigned stgK = sbase + (unsigned)s * A_STG_B;

            // ---- S = Q K^T (pre-scaled, log2 domain) ----
            float sreg[2][8][4];
            #pragma unroll
            for (int im = 0; im < 2; im++)
                #pragma unroll
                for (int in = 0; in < 8; in++)
                    #pragma unroll
                    for (int r = 0; r < 4; r++) sreg[im][in][r] = 0.f;

            #pragma unroll
            for (int ks8 = 0; ks8 < 4; ks8++) {
                const unsigned ko = (unsigned)ks8 * 32u;
                unsigned qa[2][4], kb[8][2];
                #pragma unroll
                for (int im = 0; im < 2; im++)
                    ldsm4(qa[im], sbase + qRel[im] + ko);
                #pragma unroll
                for (int j = 0; j < 4; j++)
                    ldsm4(&kb[2*j][0], stgK + kRel[j] + ko);
                #pragma unroll
                for (int im = 0; im < 2; im++)
                    #pragma unroll
                    for (int in = 0; in < 8; in++)
                        mma16(sreg[im][in], qa[im], kb[in]);
            }

            // ---- causal mask + row max (fp32) ----
            const bool needmask = (kt + 63 > wrow_min);
            float mx[2][2];
            #pragma unroll
            for (int im = 0; im < 2; im++) {
                const int rqa = wrow_min + im * 16 + g;
                const int rqb = rqa + 8;
                float a0 = -INFINITY, a1 = -INFINITY;
                #pragma unroll
                for (int in = 0; in < 8; in++) {
                    int c = kt + in * 8 + 2 * t;
                    float x0 = sreg[im][in][0];
                    float x1 = sreg[im][in][1];
                    float x2 = sreg[im][in][2];
                    float x3 = sreg[im][in][3];
                    if (needmask) {
                        if (c     > rqa) x0 = -INFINITY;
                        if (c + 1 > rqa) x1 = -INFINITY;
                        if (c     > rqb) x2 = -INFINITY;
                        if (c + 1 > rqb) x3 = -INFINITY;
                    }
                    sreg[im][in][0] = x0; sreg[im][in][1] = x1;
                    sreg[im][in][2] = x2; sreg[im][in][3] = x3;
                    a0 = fmaxf(a0, fmaxf(x0, x1));
                    a1 = fmaxf(a1, fmaxf(x2, x3));
                }
                a0 = fmaxf(a0, __shfl_xor_sync(0xffffffffu, a0, 1));
                a0 = fmaxf(a0, __shfl_xor_sync(0xffffffffu, a0, 2));
                a1 = fmaxf(a1, __shfl_xor_sync(0xffffffffu, a1, 1));
                a1 = fmaxf(a1, __shfl_xor_sync(0xffffffffu, a1, 2));
                mx[im][0] = a0; mx[im][1] = a1;
            }

            float cor[2][2];
            #pragma unroll
            for (int im = 0; im < 2; im++)
                #pragma unroll
                for (int hf = 0; hf < 2; hf++) {
                    float nm = fmaxf(m[im][hf], mx[im][hf]);
                    cor[im][hf] = ex2(m[im][hf] - nm);
                    m[im][hf] = nm;
                }

            // ---- P = 2^(x-m) via f16x2 MUFU; pk is PV-A-fragment-ready ----
            unsigned pk[2][8][2];
            #pragma unroll
            for (int im = 0; im < 2; im++) {
                const unsigned mh0 = packh2(m[im][0], m[im][0]);
                const unsigned mh1 = packh2(m[im][1], m[im][1]);
                #pragma unroll
                for (int in = 0; in < 8; in++) {
                    unsigned xa = packh2(sreg[im][in][0], sreg[im][in][1]);
                    unsigned xb = packh2(sreg[im][in][2], sreg[im][in][3]);
                    pk[im][in][0] = ex2h2(hsub2(xa, mh0));
                    pk[im][in][1] = ex2h2(hsub2(xb, mh1));
                }
            }

            // rescale O (incl. sum column 8)
            #pragma unroll
            for (int im = 0; im < 2; im++)
                #pragma unroll
                for (int in = 0; in < 9; in++) {
                    o[im][in][0] *= cor[im][0]; o[im][in][1] *= cor[im][0];
                    o[im][in][2] *= cor[im][1]; o[im][in][3] *= cor[im][1];
                }

            // ---- O += P V  (+ row sums via ones column) ----
            const unsigned stgV = sbase + (unsigned)s * A_STG_B;
            #pragma unroll
            for (int j2 = 0; j2 < 4; j2++) {              // kv k-steps of 16
                const unsigned kvo = (unsigned)j2 * 2304u;  // 16 kv-rows * 144B
                unsigned vb[8][2];
                #pragma unroll
                for (int j = 0; j < 4; j++)
                    ldsm4t(&vb[2*j][0], stgV + vRel[j] + kvo);
                #pragma unroll
                for (int im = 0; im < 2; im++) {
                    unsigned a[4];
                    a[0] = pk[im][2*j2  ][0];
                    a[1] = pk[im][2*j2  ][1];
                    a[2] = pk[im][2*j2+1][0];
                    a[3] = pk[im][2*j2+1][1];
                    #pragma unroll
                    for (int in = 0; in < 8; in++)
                        mma16(o[im][in], a, vb[in]);
                    mma16(o[im][8], a, ones_b);           // row sums
                }
            }
        }
    }

    // ---- normalize by l = o[im][8], write half2 merged-head output ----
    const int b = bh >> 4, h = bh & 15;
    #pragma unroll
    for (int im = 0; im < 2; im++) {
        float inv0 = 1.f / o[im][8][0];
        float inv1 = 1.f / o[im][8][2];
        int r0 = q0 + warp * 32 + im * 16 + g;
        #pragma unroll
        for (int in = 0; in < 8; in++) {
            int cu = h * 32 + in * 4 + t;             // half2 unit col
            size_t base0 = ((size_t)(b * TT_ + r0)     * (CC_/2)) + cu;
            size_t base1 = ((size_t)(b * TT_ + r0 + 8) * (CC_/2)) + cu;
            g_Yc[base0] = packh2(o[im][in][0] * inv0, o[im][in][1] * inv0);
            g_Yc[base1] = packh2(o[im][in][2] * inv1, o[im][in][3] * inv1);
        }
    }
}

// ============================================================================
// launch
// ============================================================================
extern "C" void kernel_launch(void* const* d_in, const int* in_sizes, int n_in,
                              void* d_out, int out_size)
{
    const float* X  = (const float*)d_in[0];
    const float* Wq = (const float*)d_in[1];
    const float* Wk = (const float*)d_in[2];
    const float* Wv = (const float*)d_in[3];
    const float* Wo = (const float*)d_in[4];
    float* out = (float*)d_out;

    cudaFuncSetAttribute(gemm_fp16<1>, cudaFuncAttributeMaxDynamicSharedMemorySize,
                         GEMM_SMEM_BYTES);
    cudaFuncSetAttribute(gemm_fp16<0>, cudaFuncAttributeMaxDynamicSharedMemorySize,
                         GEMM_SMEM_BYTES);
    cudaFuncSetAttribute(attn_kernel, cudaFuncAttributeMaxDynamicSharedMemorySize,
                         ATTN_SMEM_BYTES);

    unsigned *Xt = nullptr, *Wt = nullptr, *Yc = nullptr;
    cudaGetSymbolAddress((void**)&Xt, g_Xt);
    cudaGetSymbolAddress((void**)&Wt, g_Wt);
    cudaGetSymbolAddress((void**)&Yc, g_Yc);

    // 0) fp16 pre-conversion
    conv_kernel<<<8192, 256>>>((const float4*)X, (const float4*)Wq,
                               (const float4*)Wk, (const float4*)Wv,
                               (const float4*)Wo);

    // 1) QKV: M=4096, N=3072 (24 tiles of 128), K=1024
    gemm_fp16<1><<<dim3(24, 32), 128, GEMM_SMEM_BYTES>>>(
        (const __half*)Xt, (const __half*)Wt, nullptr);

    // 2) attention: grid = (q-tiles=16, b*h=32)
    attn_kernel<<<dim3(16, 32), 128, ATTN_SMEM_BYTES>>>();

    // 3) output projection: M=4096, N=1024 (8 tiles of 128), K=1024
    gemm_fp16<0><<<dim3(8, 32), 128, GEMM_SMEM_BYTES>>>(
        (const __half*)Yc, (const __half*)Wt + 3*1024*1024, out);
}

// round 9
// speedup vs baseline: 2.2266x; 1.0142x over previous
#include <cuda_runtime.h>
#include <cuda_fp16.h>
#include <cstdint>
#include <cstdio>

// ---------------- problem constants ----------------
#define BB_ 2
#define TT_ 2048
#define CC_ 1024
#define HH_ 16
#define DD_ 64

// exp(s/8) = 2^(s * log2(e)/8); folded into Q at the QKV epilogue
#define SOFTMAX_SCL 0.18033688011112042f

// ---------------- scratch: fp16 stored as unsigned (half2 units) ----------------
__device__ __align__(16) unsigned g_Xt[BB_*TT_*CC_/2];      // X fp16 [m][k]
__device__ __align__(16) unsigned g_Wt[4*CC_*CC_/2];        // Wq|Wk|Wv|Wo fp16 [n][k]
__device__ __align__(16) unsigned g_Q [BB_*HH_*TT_*DD_/2];  // [b,h,t,d]  (pre-scaled)
__device__ __align__(16) unsigned g_K [BB_*HH_*TT_*DD_/2];  // [b,h,t,d]
__device__ __align__(16) unsigned g_V [BB_*HH_*TT_*DD_/2];  // [b,h,t,d]
__device__ __align__(16) unsigned g_Yc[BB_*TT_*CC_/2];      // merged heads [b,t,c]

// ---------------- helpers ----------------
__device__ __forceinline__ float ex2(float x) {
    float y;
    asm("ex2.approx.f32 %0, %1;" : "=f"(y) : "f"(x));
    return y;
}
__device__ __forceinline__ unsigned ex2h2(unsigned x) {
    unsigned y;
    asm("ex2.approx.f16x2 %0, %1;" : "=r"(y) : "r"(x));
    return y;
}
__device__ __forceinline__ unsigned hsub2(unsigned a, unsigned b) {
    unsigned y;
    asm("sub.f16x2 %0, %1, %2;" : "=r"(y) : "r"(a), "r"(b));
    return y;
}
__device__ __forceinline__ unsigned packh2(float a, float b) {
    __half2 h = __floats2half2_rn(a, b);
    return *(unsigned*)&h;
}
__device__ __forceinline__ void mma16(float* d, const unsigned* a, const unsigned* b) {
    asm volatile(
        "mma.sync.aligned.m16n8k16.row.col.f32.f16.f16.f32 "
        "{%0,%1,%2,%3},{%4,%5,%6,%7},{%8,%9},{%0,%1,%2,%3};"
        : "+f"(d[0]), "+f"(d[1]), "+f"(d[2]), "+f"(d[3])
        : "r"(a[0]), "r"(a[1]), "r"(a[2]), "r"(a[3]),
          "r"(b[0]), "r"(b[1]));
}
__device__ __forceinline__ void ldsm4(unsigned* r, unsigned addr) {
    asm volatile("ldmatrix.sync.aligned.m8n8.x4.shared.b16 {%0,%1,%2,%3}, [%4];"
        : "=r"(r[0]), "=r"(r[1]), "=r"(r[2]), "=r"(r[3]) : "r"(addr));
}
__device__ __forceinline__ void ldsm4t(unsigned* r, unsigned addr) {
    asm volatile("ldmatrix.sync.aligned.m8n8.x4.trans.shared.b16 {%0,%1,%2,%3}, [%4];"
        : "=r"(r[0]), "=r"(r[1]), "=r"(r[2]), "=r"(r[3]) : "r"(addr));
}
__device__ __forceinline__ void cpa(unsigned dst, const void* src) {
    asm volatile("cp.async.cg.shared.global [%0], [%1], 16;" :: "r"(dst), "l"(src));
}
#define CP_COMMIT() asm volatile("cp.async.commit_group;")
#define CP_WAIT1()  asm volatile("cp.async.wait_group 1;")
#define CP_WAIT0()  asm volatile("cp.async.wait_group 0;")
__device__ __forceinline__ unsigned smem_u32(const void* p) {
    return (unsigned)__cvta_generic_to_shared(p);
}

// ============================================================================
// one-shot fp16 conversion: X (1M float4) + 4 weights (256K float4 each)
// ============================================================================
__global__ void __launch_bounds__(256) conv_kernel(
    const float4* __restrict__ X,  const float4* __restrict__ Wq,
    const float4* __restrict__ Wk, const float4* __restrict__ Wv,
    const float4* __restrict__ Wo)
{
    int i = blockIdx.x * 256 + threadIdx.x;          // 0 .. 2M-1
    const float4* src;
    uint2* dst;
    if (i < (1 << 20)) {
        src = X + i;
        dst = (uint2*)g_Xt + i;
    } else {
        int j = i - (1 << 20);
        int w = j >> 18, r = j & 0x3FFFF;
        const float4* s4 = (w == 0) ? Wq : (w == 1) ? Wk : (w == 2) ? Wv : Wo;
        src = s4 + r;
        dst = (uint2*)g_Wt + (w << 18) + r;
    }
    float4 v = *src;
    *dst = make_uint2(packh2(v.x, v.y), packh2(v.z, v.w));
}

// ============================================================================
// fp16 GEMM: C[m,n] = sum_k A[m,k]*B[n,k]  (NT), K=1024.
// CTA 128x128, 4 warps (2m x 2n), warp tile 64x64, m16n8k16 + ldmatrix.x4.
// 3-stage cp.async ring, wait_group(1): one full chunk of prefetch slack.
// Single __syncthreads per k-chunk. 128 thr; 110.6KB smem -> 2 CTAs/SM.
// MODE 1: epilogue -> g_Q (pre-scaled) / g_K / g_V (all [b,h,t,d], coalesced).
// MODE 0: A=g_Yc, writes fp32 Cout.
// ============================================================================
#define G_ROW_B 144u
#define G_A_B   18432u          // A block bytes (128*144)
#define G_STG_B 36864u          // A+B per stage
#define GEMM_SMEM_BYTES (3*36864)

template<int MODE>
__global__ void __launch_bounds__(128, 2) gemm_fp16(
    const __half* __restrict__ A,
    const __half* __restrict__ B,
    float* __restrict__ Cout)
{
    extern __shared__ unsigned smem[];
    const unsigned sbase = smem_u32(smem);

    const int tid  = threadIdx.x;
    const int bm   = blockIdx.y * 128;
    const int bn   = blockIdx.x * 128;
    const int warp = tid >> 5, lane = tid & 31;
    const int g = lane >> 2, t = lane & 3;
    const int wm = (warp & 1) * 64;          // warp m offset
    const int wn = (warp >> 1) * 64;         // warp n offset

    const __half* Ap = A + (size_t)bm * 1024;
    const __half* Bp = B + (size_t)bn * 1024;

    float acc[4][8][4];
    #pragma unroll
    for (int i = 0; i < 4; i++)
        #pragma unroll
        for (int j = 0; j < 8; j++)
            #pragma unroll
            for (int r = 0; r < 4; r++) acc[i][j][r] = 0.f;

    // ldmatrix per-lane relative byte offsets
    unsigned aRel[4], bRel[4];
    {
        int rA = (lane & 15), kA = (lane >> 4) * 8;
        #pragma unroll
        for (int im = 0; im < 4; im++)
            aRel[im] = (unsigned)((wm + im * 16 + rA) * 72 + kA) * 2u;
        int rB = ((lane >> 4) & 1) * 8 + (lane & 7);
        int kB = ((lane >> 3) & 1) * 8;
        #pragma unroll
        for (int j = 0; j < 4; j++)
            bRel[j] = G_A_B + (unsigned)((wn + j * 16 + rB) * 72 + kB) * 2u;
    }

    auto load_stage = [&](int s, int k0) {
        const unsigned st = sbase + (unsigned)s * G_STG_B;
        #pragma unroll
        for (int i = 0; i < 8; i++) {                       // A: 1024 chunks
            int id = tid + (i << 7);
            int r = id >> 3, c = id & 7;
            cpa(st + (unsigned)r * G_ROW_B + (unsigned)c * 16u,
                Ap + (size_t)r * 1024 + k0 + c * 8);
        }
        #pragma unroll
        for (int i = 0; i < 8; i++) {                       // B: 1024 chunks
            int id = tid + (i << 7);
            int r = id >> 3, c = id & 7;
            cpa(st + G_A_B + (unsigned)r * G_ROW_B + (unsigned)c * 16u,
                Bp + (size_t)r * 1024 + k0 + c * 8);
        }
    };

    load_stage(0, 0);
    CP_COMMIT();
    load_stage(1, 64);
    CP_COMMIT();

    int s = 0;
    #pragma unroll 1
    for (int i = 0; i < 16; ++i) {
        if (i + 1 < 16) { CP_WAIT1(); } else { CP_WAIT0(); }
        __syncthreads();
        if (i + 2 < 16) {
            int s2 = s + 2; if (s2 >= 3) s2 -= 3;
            load_stage(s2, (i + 2) * 64);
            CP_COMMIT();
        }

        const unsigned stg = sbase + (unsigned)s * G_STG_B;
        #pragma unroll
        for (int ks8 = 0; ks8 < 4; ks8++) {                 // 4 k-steps of 16
            const unsigned ko = (unsigned)ks8 * 32u;        // 16 halves = 32B
            unsigned afr[4][4], bfr[8][2];
            #pragma unroll
            for (int im = 0; im < 4; im++)
                ldsm4(afr[im], stg + aRel[im] + ko);
            #pragma unroll
            for (int j = 0; j < 4; j++)
                ldsm4(&bfr[2*j][0], stg + bRel[j] + ko);
            #pragma unroll
            for (int im = 0; im < 4; im++)
                #pragma unroll
                for (int in = 0; in < 8; in++)
                    mma16(acc[im][in], afr[im], bfr[in]);
        }
        if (++s >= 3) s = 0;
    }

    // ---------------- epilogue ----------------
    if (MODE == 0) {
        #pragma unroll
        for (int im = 0; im < 4; im++) {
            #pragma unroll
            for (int in = 0; in < 8; in++) {
                int r0 = bm + wm + im * 16 + g;
                int c0 = bn + wn + in * 8 + 2 * t;
                *(float2*)(Cout + (size_t)r0 * 1024 + c0) =
                    make_float2(acc[im][in][0], acc[im][in][1]);
                *(float2*)(Cout + (size_t)(r0 + 8) * 1024 + c0) =
                    make_float2(acc[im][in][2], acc[im][in][3]);
            }
        }
    } else {
        const int which = bn >> 10;
        const int nloc  = bn & 1023;
        const float qs = (which == 0) ? SOFTMAX_SCL : 1.f;  // fold softmax scale into Q
        unsigned* dst = (which == 0) ? g_Q : (which == 1) ? g_K : g_V;
        #pragma unroll
        for (int im = 0; im < 4; im++) {
            #pragma unroll
            for (int in = 0; in < 8; in++) {
                int r0 = bm + wm + im * 16 + g;      // m = b*2048 + t
                int b  = r0 >> 11, tt = r0 & 2047;
                int n0 = nloc + wn + in * 8 + 2 * t;
                int h  = n0 >> 6, d = n0 & 63;
                size_t base = ((size_t)(b * HH_ + h) * TT_ + tt) * (DD_/2) + (d >> 1);
                dst[base] = packh2(acc[im][in][0] * qs, acc[im][in][1] * qs);
                dst[base + 8 * (DD_/2)] = packh2(acc[im][in][2] * qs, acc[im][in][3] * qs);
            }
        }
    }
}

// ============================================================================
// Flash attention (causal), register-resident P, f16x2 softmax,
// row sums via ones-column mma, V via ldmatrix.x4.trans.
// CTA = 128 q-rows of one (b,h), 4 warps x 32 q-rows, 128 thr.
// K/V 64-row tiles in a 3-stage cp.async ring (wait_group 1), single sync/tile.
// 73.7KB smem -> 2 CTAs/SM.
// ============================================================================
// bytes: sQ[128][72h] @0 (18432), sK[3][64][72h] @18432, sV[3][64][72h] @46080
#define A_K_OFF 18432u
#define A_V_OFF 46080u
#define A_STG_B 9216u
#define ATTN_SMEM_BYTES 73728

__global__ void __launch_bounds__(128, 2) attn_kernel()
{
    extern __shared__ unsigned smem[];
    const unsigned sbase = smem_u32(smem);

    const int bh = blockIdx.y;                    // b*16 + h
    const int qt = gridDim.x - 1 - blockIdx.x;    // biggest tiles first
    const int q0 = qt * 128;
    const int nkt = (q0 >> 6) + 2;                // k-tiles: kt = 0 .. q0+64  (>=2)

    const __half* Qp = (const __half*)g_Q + (size_t)bh * TT_ * DD_;
    const __half* Kp = (const __half*)g_K + (size_t)bh * TT_ * DD_;
    const __half* Vp = (const __half*)g_V + (size_t)bh * TT_ * DD_;

    const int tid = threadIdx.x;
    const int warp = tid >> 5, lane = tid & 31;
    const int g = lane >> 2, t = lane & 3;

    // ldmatrix per-lane relative offsets
    unsigned qRel[2], kRel[4], vRel[4];
    {
        int rA = (lane & 15), kA = (lane >> 4) * 8;
        #pragma unroll
        for (int im = 0; im < 2; im++)
            qRel[im] = (unsigned)((warp * 32 + im * 16 + rA) * 72 + kA) * 2u;
        int rB = ((lane >> 4) & 1) * 8 + (lane & 7);
        int kB = ((lane >> 3) & 1) * 8;
        #pragma unroll
        for (int j = 0; j < 4; j++)
            kRel[j] = A_K_OFF + (unsigned)((j * 16 + rB) * 72 + kB) * 2u;
        // V (trans): lane -> kv row (lane&15), d col = j*16 + (lane>>4)*8
        int rV = lane & 15, cV = (lane >> 4) * 8;
        #pragma unroll
        for (int j = 0; j < 4; j++)
            vRel[j] = A_V_OFF + (unsigned)(rV * 72 + j * 16 + cV) * 2u;
    }

    auto load_kv = [&](int s, int kt) {
        #pragma unroll
        for (int i = 0; i < 4; i++) {
            int id = tid + (i << 7);
            int r = id >> 3, c = id & 7;
            cpa(sbase + A_K_OFF + (unsigned)s * A_STG_B + (unsigned)r * 144u + (unsigned)c * 16u,
                Kp + (size_t)(kt + r) * DD_ + c * 8);
            cpa(sbase + A_V_OFF + (unsigned)s * A_STG_B + (unsigned)r * 144u + (unsigned)c * 16u,
                Vp + (size_t)(kt + r) * DD_ + c * 8);
        }
    };

    // ---- prologue: Q (128x64) + KV stage 0, then KV stage 1 ----
    {
        #pragma unroll
        for (int i = 0; i < 8; i++) {                     // Q: 1024 chunks
            int id = tid + (i << 7);
            int r = id >> 3, c = id & 7;
            cpa(sbase + (unsigned)r * 144u + (unsigned)c * 16u,
                Qp + (size_t)(q0 + r) * DD_ + c * 8);
        }
        load_kv(0, 0);
        CP_COMMIT();
        load_kv(1, 64);
        CP_COMMIT();
    }

    float m[2][2];
    #pragma unroll
    for (int i = 0; i < 2; i++)
        #pragma unroll
        for (int j = 0; j < 2; j++) m[i][j] = -INFINITY;

    // o[im][0..7] = output, o[im][8] = row sums (V ones column)
    float o[2][9][4];
    #pragma unroll
    for (int im = 0; im < 2; im++)
        #pragma unroll
        for (int in = 0; in < 9; in++)
            #pragma unroll
            for (int r = 0; r < 4; r++) o[im][in][r] = 0.f;

    const unsigned ones_b[2] = {0x3C003C00u, 0x3C003C00u};  // half2(1,1)
    const int wrow_min = q0 + warp * 32;

    int s = 0;
    #pragma unroll 1
    for (int it = 0; it < nkt; ++it) {
        const int kt = it * 64;
        if (it + 1 < nkt) { CP_WAIT1(); } else { CP_WAIT0(); }
        __syncthreads();
        if (it + 2 < nkt) {
            int s2 = s + 2; if (s2 >= 3) s2 -= 3;
            load_kv(s2, kt + 128);
            CP_COMMIT();
        }

        if (kt < wrow_min + 32) {
            const unsigned stgK = sbase + (unsigned)s * A_STG_B;  // rel offs carry K/V base

            // ---- S = Q K^T (pre-scaled, log2 domain) ----
            float sreg[2][8][4];
            #pragma unroll
            for (int im = 0; im < 2; im++)
                #pragma unroll
                for (int in = 0; in < 8; in++)
                    #pragma unroll
                    for (int r = 0; r < 4; r++) sreg[im][in][r] = 0.f;

            #pragma unroll
            for (int ks8 = 0; ks8 < 4; ks8++) {
                const unsigned ko = (unsigned)ks8 * 32u;
                unsigned qa[2][4], kb[8][2];
                #pragma unroll
                for (int im = 0; im < 2; im++)
                    ldsm4(qa[im], sbase + qRel[im] + ko);
                #pragma unroll
                for (int j = 0; j < 4; j++)
                    ldsm4(&kb[2*j][0], stgK + kRel[j] + ko);
                #pragma unroll
                for (int im = 0; im < 2; im++)
                    #pragma unroll
                    for (int in = 0; in < 8; in++)
                        mma16(sreg[im][in], qa[im], kb[in]);
            }

            // ---- causal mask + row max (fp32) ----
            const bool needmask = (kt + 63 > wrow_min);
            float mx[2][2];
            #pragma unroll
            for (int im = 0; im < 2; im++) {
                const int rqa = wrow_min + im * 16 + g;
                const int rqb = rqa + 8;
                float a0 = -INFINITY, a1 = -INFINITY;
                #pragma unroll
                for (int in = 0; in < 8; in++) {
                    int c = kt + in * 8 + 2 * t;
                    float x0 = sreg[im][in][0];
                    float x1 = sreg[im][in][1];
                    float x2 = sreg[im][in][2];
                    float x3 = sreg[im][in][3];
                    if (needmask) {
                        if (c     > rqa) x0 = -INFINITY;
                        if (c + 1 > rqa) x1 = -INFINITY;
                        if (c     > rqb) x2 = -INFINITY;
                        if (c + 1 > rqb) x3 = -INFINITY;
                    }
                    sreg[im][in][0] = x0; sreg[im][in][1] = x1;
                    sreg[im][in][2] = x2; sreg[im][in][3] = x3;
                    a0 = fmaxf(a0, fmaxf(x0, x1));
                    a1 = fmaxf(a1, fmaxf(x2, x3));
                }
                a0 = fmaxf(a0, __shfl_xor_sync(0xffffffffu, a0, 1));
                a0 = fmaxf(a0, __shfl_xor_sync(0xffffffffu, a0, 2));
                a1 = fmaxf(a1, __shfl_xor_sync(0xffffffffu, a1, 1));
                a1 = fmaxf(a1, __shfl_xor_sync(0xffffffffu, a1, 2));
                mx[im][0] = a0; mx[im][1] = a1;
            }

            float cor[2][2];
            #pragma unroll
            for (int im = 0; im < 2; im++)
                #pragma unroll
                for (int hf = 0; hf < 2; hf++) {
                    float nm = fmaxf(m[im][hf], mx[im][hf]);
                    cor[im][hf] = ex2(m[im][hf] - nm);
                    m[im][hf] = nm;
                }

            // ---- P = 2^(x-m) via f16x2 MUFU; pk is PV-A-fragment-ready ----
            unsigned pk[2][8][2];
            #pragma unroll
            for (int im = 0; im < 2; im++) {
                const unsigned mh0 = packh2(m[im][0], m[im][0]);
                const unsigned mh1 = packh2(m[im][1], m[im][1]);
                #pragma unroll
                for (int in = 0; in < 8; in++) {
                    unsigned xa = packh2(sreg[im][in][0], sreg[im][in][1]);
                    unsigned xb = packh2(sreg[im][in][2], sreg[im][in][3]);
                    pk[im][in][0] = ex2h2(hsub2(xa, mh0));
                    pk[im][in][1] = ex2h2(hsub2(xb, mh1));
                }
            }

            // rescale O (incl. sum column 8)
            #pragma unroll
            for (int im = 0; im < 2; im++)
                #pragma unroll
                for (int in = 0; in < 9; in++) {
                    o[im][in][0] *= cor[im][0]; o[im][in][1] *= cor[im][0];
                    o[im][in][2] *= cor[im][1]; o[im][in][3] *= cor[im][1];
                }

            // ---- O += P V  (+ row sums via ones column) ----
            const unsigned stgV = sbase + (unsigned)s * A_STG_B;
            #pragma unroll
            for (int j2 = 0; j2 < 4; j2++) {              // kv k-steps of 16
                const unsigned kvo = (unsigned)j2 * 2304u;  // 16 kv-rows * 144B
                unsigned vb[8][2];
                #pragma unroll
                for (int j = 0; j < 4; j++)
                    ldsm4t(&vb[2*j][0], stgV + vRel[j] + kvo);
                #pragma unroll
                for (int im = 0; im < 2; im++) {
                    unsigned a[4];
                    a[0] = pk[im][2*j2  ][0];
                    a[1] = pk[im][2*j2  ][1];
                    a[2] = pk[im][2*j2+1][0];
                    a[3] = pk[im][2*j2+1][1];
                    #pragma unroll
                    for (int in = 0; in < 8; in++)
                        mma16(o[im][in], a, vb[in]);
                    mma16(o[im][8], a, ones_b);           // row sums
                }
            }
        }
        if (++s >= 3) s = 0;
    }

    // ---- normalize by l = o[im][8], write half2 merged-head output ----
    const int b = bh >> 4, h = bh & 15;
    #pragma unroll
    for (int im = 0; im < 2; im++) {
        float inv0 = 1.f / o[im][8][0];
        float inv1 = 1.f / o[im][8][2];
        int r0 = q0 + warp * 32 + im * 16 + g;
        #pragma unroll
        for (int in = 0; in < 8; in++) {
            int cu = h * 32 + in * 4 + t;             // half2 unit col
            size_t base0 = ((size_t)(b * TT_ + r0)     * (CC_/2)) + cu;
            size_t base1 = ((size_t)(b * TT_ + r0 + 8) * (CC_/2)) + cu;
            g_Yc[base0] = packh2(o[im][in][0] * inv0, o[im][in][1] * inv0);
            g_Yc[base1] = packh2(o[im][in][2] * inv1, o[im][in][3] * inv1);
        }
    }
}

// ============================================================================
// launch
// ============================================================================
extern "C" void kernel_launch(void* const* d_in, const int* in_sizes, int n_in,
                              void* d_out, int out_size)
{
    const float* X  = (const float*)d_in[0];
    const float* Wq = (const float*)d_in[1];
    const float* Wk = (const float*)d_in[2];
    const float* Wv = (const float*)d_in[3];
    const float* Wo = (const float*)d_in[4];
    float* out = (float*)d_out;

    cudaFuncSetAttribute(gemm_fp16<1>, cudaFuncAttributeMaxDynamicSharedMemorySize,
                         GEMM_SMEM_BYTES);
    cudaFuncSetAttribute(gemm_fp16<0>, cudaFuncAttributeMaxDynamicSharedMemorySize,
                         GEMM_SMEM_BYTES);
    cudaFuncSetAttribute(attn_kernel, cudaFuncAttributeMaxDynamicSharedMemorySize,
                         ATTN_SMEM_BYTES);

    unsigned *Xt = nullptr, *Wt = nullptr, *Yc = nullptr;
    cudaGetSymbolAddress((void**)&Xt, g_Xt);
    cudaGetSymbolAddress((void**)&Wt, g_Wt);
    cudaGetSymbolAddress((void**)&Yc, g_Yc);

    // 0) fp16 pre-conversion
    conv_kernel<<<8192, 256>>>((const float4*)X, (const float4*)Wq,
                               (const float4*)Wk, (const float4*)Wv,
                               (const float4*)Wo);

    // 1) QKV: M=4096, N=3072 (24 tiles of 128), K=1024
    gemm_fp16<1><<<dim3(24, 32), 128, GEMM_SMEM_BYTES>>>(
        (const __half*)Xt, (const __half*)Wt, nullptr);

    // 2) attention: grid = (q-tiles=16, b*h=32)
    attn_kernel<<<dim3(16, 32), 128, ATTN_SMEM_BYTES>>>();

    // 3) output projection: M=4096, N=1024 (8 tiles of 128), K=1024
    gemm_fp16<0><<<dim3(8, 32), 128, GEMM_SMEM_BYTES>>>(
        (const __half*)Yc, (const __half*)Wt + 3*1024*1024, out);
}